// round 1
// baseline (speedup 1.0000x reference)
#include <cuda_runtime.h>
#include <cstddef>

#define NB 8
#define NN 2048
#define NR 16384          // NB*NN rows
#define LRA 0.2f          // leaky relu slope

// ---------------- device scratch (static, no allocation) ----------------
__device__ float g_h[NR * 256];        // per-layer h (both heads concatenated)
__device__ float g_xmid[NR * 256];     // layer-0 output / layer-1 input
__device__ float g_Wcat[2][256 * 256]; // [layer][k][head*128+d]
__device__ float g_bcat[2][256];
__device__ float g_aL[2][2][128];
__device__ float g_aR[2][2][128];
__device__ float g_hl[2 * NR];         // [head][row]
__device__ float g_hr[2 * NR];
__device__ float g_rs[2 * NR];         // sorted hr per (head,b)
__device__ int   g_sidx[2 * NR];       // original index of sorted entry
__device__ int   g_mcnt[2 * NR];       // #entries with r < -hl_i
__device__ float g_P1[2 * NR * 128];   // prefix sums of e^{r} * h   [head][b][j][d]
__device__ float g_P2[2 * NR * 128];   // prefix sums of e^{a r} * h
__device__ float g_Z1[2 * NR];
__device__ float g_Z2[2 * NR];

// ---------------- pack weights into fused layouts ----------------
__global__ void pack_kernel(
    const float* W00, const float* b00, const float* a00,
    const float* W01, const float* b01, const float* a01,
    const float* W10, const float* b10, const float* a10,
    const float* W11, const float* b11, const float* a11)
{
    const float* Ws[2][2] = {{W00, W01}, {W10, W11}};
    const float* bs[2][2] = {{b00, b01}, {b10, b11}};
    const float* as[2][2] = {{a00, a01}, {a10, a11}};
    int tid = blockIdx.x * blockDim.x + threadIdx.x;
    int nth = gridDim.x * blockDim.x;
    for (int idx = tid; idx < 2 * 256 * 256; idx += nth) {
        int layer = idx >> 16;
        int rem = idx & 0xFFFF;
        int k = rem >> 8, c = rem & 255;
        g_Wcat[layer][rem] = Ws[layer][c >> 7][k * 128 + (c & 127)];
    }
    for (int idx = tid; idx < 2 * 256; idx += nth) {
        int layer = idx >> 8, c = idx & 255;
        g_bcat[layer][c] = bs[layer][c >> 7][c & 127];
    }
    for (int idx = tid; idx < 2 * 2 * 128; idx += nth) {
        int layer = idx >> 8, head = (idx >> 7) & 1, d = idx & 127;
        g_aL[layer][head][d] = as[layer][head][d];
        g_aR[layer][head][d] = as[layer][head][128 + d];
    }
}

// ---------------- fused 2-head GEMM: h = X @ Wcat + bcat ----------------
// M=16384, K=256, Ncols=256. 128x128 tiles, 256 threads, 8x8 micro-tile.
__global__ __launch_bounds__(256) void gemm_kernel(const float* __restrict__ Xin, int layer)
{
    const float* X = Xin ? Xin : g_xmid;
    __shared__ float As[2][16][132];
    __shared__ float Bs[2][16][128];
    int t = threadIdx.x;
    int tx = t & 15, ty = t >> 4;
    int m0 = blockIdx.y * 128, n0 = blockIdx.x * 128;
    const float* Wp = g_Wcat[layer];

    float acc[8][8];
#pragma unroll
    for (int i = 0; i < 8; i++)
#pragma unroll
        for (int j = 0; j < 8; j++) acc[i][j] = 0.f;

    // initial load (k-tile 0) into buffer 0
#pragma unroll
    for (int r = 0; r < 2; r++) {
        int qq = t + r * 256;
        int row = qq >> 2, kq = qq & 3;
        float4 v = *(const float4*)(X + (size_t)(m0 + row) * 256 + kq * 4);
        As[0][kq * 4 + 0][row] = v.x;
        As[0][kq * 4 + 1][row] = v.y;
        As[0][kq * 4 + 2][row] = v.z;
        As[0][kq * 4 + 3][row] = v.w;
    }
#pragma unroll
    for (int r = 0; r < 2; r++) {
        int qq = t + r * 256;
        int row = qq >> 5, nq = qq & 31;
        *(float4*)&Bs[0][row][nq * 4] =
            *(const float4*)(Wp + (size_t)row * 256 + n0 + nq * 4);
    }
    __syncthreads();

    for (int kt = 0; kt < 16; kt++) {
        int cur = kt & 1;
        if (kt < 15) {
            int nxt = cur ^ 1;
            int k0 = (kt + 1) * 16;
#pragma unroll
            for (int r = 0; r < 2; r++) {
                int qq = t + r * 256;
                int row = qq >> 2, kq = qq & 3;
                float4 v = *(const float4*)(X + (size_t)(m0 + row) * 256 + k0 + kq * 4);
                As[nxt][kq * 4 + 0][row] = v.x;
                As[nxt][kq * 4 + 1][row] = v.y;
                As[nxt][kq * 4 + 2][row] = v.z;
                As[nxt][kq * 4 + 3][row] = v.w;
            }
#pragma unroll
            for (int r = 0; r < 2; r++) {
                int qq = t + r * 256;
                int row = qq >> 5, nq = qq & 31;
                *(float4*)&Bs[nxt][row][nq * 4] =
                    *(const float4*)(Wp + (size_t)(k0 + row) * 256 + n0 + nq * 4);
            }
        }
#pragma unroll
        for (int kk = 0; kk < 16; kk++) {
            float a8[8], b8[8];
            *(float4*)&a8[0] = *(const float4*)&As[cur][kk][ty * 8];
            *(float4*)&a8[4] = *(const float4*)&As[cur][kk][ty * 8 + 4];
            *(float4*)&b8[0] = *(const float4*)&Bs[cur][kk][tx * 8];
            *(float4*)&b8[4] = *(const float4*)&Bs[cur][kk][tx * 8 + 4];
#pragma unroll
            for (int i = 0; i < 8; i++)
#pragma unroll
                for (int j = 0; j < 8; j++)
                    acc[i][j] = fmaf(a8[i], b8[j], acc[i][j]);
        }
        __syncthreads();
    }

    float4 bia = *(const float4*)&g_bcat[layer][n0 + tx * 8];
    float4 bib = *(const float4*)&g_bcat[layer][n0 + tx * 8 + 4];
#pragma unroll
    for (int i = 0; i < 8; i++) {
        int row = m0 + ty * 8 + i;
        float4 o0, o1;
        o0.x = acc[i][0] + bia.x; o0.y = acc[i][1] + bia.y;
        o0.z = acc[i][2] + bia.z; o0.w = acc[i][3] + bia.w;
        o1.x = acc[i][4] + bib.x; o1.y = acc[i][5] + bib.y;
        o1.z = acc[i][6] + bib.z; o1.w = acc[i][7] + bib.w;
        *(float4*)&g_h[(size_t)row * 256 + n0 + tx * 8] = o0;
        *(float4*)&g_h[(size_t)row * 256 + n0 + tx * 8 + 4] = o1;
    }
}

// ---------------- hl = h . a_l, hr = h . a_r (one warp per row,head) ---------
__global__ __launch_bounds__(256) void hlhr_kernel(int layer)
{
    int t = threadIdx.x;
    int warp = (blockIdx.x << 3) + (t >> 5);
    int lane = t & 31;
    int head = warp & 1, row = warp >> 1;
    float4 hv = *(const float4*)&g_h[(size_t)row * 256 + head * 128 + lane * 4];
    float4 al = *(const float4*)&g_aL[layer][head][lane * 4];
    float4 ar = *(const float4*)&g_aR[layer][head][lane * 4];
    float sl = hv.x * al.x + hv.y * al.y + hv.z * al.z + hv.w * al.w;
    float sr = hv.x * ar.x + hv.y * ar.y + hv.z * ar.z + hv.w * ar.w;
#pragma unroll
    for (int o = 16; o > 0; o >>= 1) {
        sl += __shfl_xor_sync(0xFFFFFFFFu, sl, o);
        sr += __shfl_xor_sync(0xFFFFFFFFu, sr, o);
    }
    if (lane == 0) {
        g_hl[head * NR + row] = sl;
        g_hr[head * NR + row] = sr;
    }
}

// ---------------- bitonic sort of hr per (head,b) ----------------
__global__ __launch_bounds__(1024) void sort_kernel()
{
    __shared__ float key[2048];
    __shared__ int   idx[2048];
    int hb = blockIdx.x;
    int head = hb >> 3, b = hb & 7;
    int t = threadIdx.x;
    int base = head * NR + b * 2048;
    for (int i = t; i < 2048; i += 1024) { key[i] = g_hr[base + i]; idx[i] = i; }
    __syncthreads();
    for (int k = 2; k <= 2048; k <<= 1) {
        for (int j = k >> 1; j > 0; j >>= 1) {
            for (int i = t; i < 2048; i += 1024) {
                int ixj = i ^ j;
                if (ixj > i) {
                    bool up = ((i & k) == 0);
                    float ka = key[i], kb = key[ixj];
                    if ((ka > kb) == up) {
                        key[i] = kb; key[ixj] = ka;
                        int ia = idx[i]; idx[i] = idx[ixj]; idx[ixj] = ia;
                    }
                }
            }
            __syncthreads();
        }
    }
    for (int i = t; i < 2048; i += 1024) {
        g_rs[base + i] = key[i];
        g_sidx[base + i] = idx[i];
    }
}

// ---------------- threshold binary search per (head,row) ----------------
__global__ __launch_bounds__(256) void msearch_kernel()
{
    int idx = blockIdx.x * blockDim.x + threadIdx.x;
    if (idx >= 2 * NR) return;
    int head = idx >> 14, row = idx & (NR - 1);
    int b = row >> 11;
    float thr = -g_hl[head * NR + row];
    const float* rs = &g_rs[head * NR + b * 2048];
    int lo = 0, hi = 2048;
    while (lo < hi) {
        int mid = (lo + hi) >> 1;
        if (rs[mid] < thr) lo = mid + 1; else hi = mid;
    }
    g_mcnt[idx] = lo;
}

// ---------------- prefix sums over sorted order ----------------
__global__ __launch_bounds__(256) void prefix_kernel()
{
    __shared__ float ew1[2048], ew2[2048];
    __shared__ int   sid[2048];
    int hb = blockIdx.x;
    int head = hb >> 3, b = hb & 7;
    int t = threadIdx.x;
    int base = head * NR + b * 2048;
    for (int j = t; j < 2048; j += 256) {
        float r = g_rs[base + j];
        ew1[j] = expf(r);
        ew2[j] = expf(LRA * r);
        sid[j] = g_sidx[base + j];
    }
    __syncthreads();
    int d = t & 127;
    bool a2 = (t >= 128);
    const float* hp = g_h + (size_t)(b * 2048) * 256 + head * 128 + d;
    float* P = (a2 ? g_P2 : g_P1) + (size_t)base * 128 + d;
    float* Z = (a2 ? g_Z2 : g_Z1) + base;
    const float* ew = a2 ? ew2 : ew1;
    float acc = 0.f, z = 0.f;
#pragma unroll 4
    for (int j = 0; j < 2048; j++) {
        int rl = sid[j];
        float v = __ldg(hp + (size_t)rl * 256);
        float w = ew[j];
        acc = fmaf(w, v, acc);
        P[(size_t)j * 128] = acc;
        if (d == 0) { z += w; Z[j] = z; }
    }
}

// ---------------- per-node O(D) lookup + ELU ----------------
__global__ __launch_bounds__(256) void lookup_kernel(float* xout)
{
    float* xo = xout ? xout : g_xmid;
    int b = blockIdx.y;
    int n0 = blockIdx.x * 64;
    int t = threadIdx.x;
    int head = t >> 7, d = t & 127;
    int base = head * NR + b * 2048;
    float p1tot = g_P1[((size_t)base + 2047) * 128 + d];
    float z1tot = g_Z1[base + 2047];
    for (int nn = 0; nn < 64; nn++) {
        int row = b * 2048 + n0 + nn;
        float c = g_hl[head * NR + row];
        float ri = g_hr[head * NR + row];
        int m = g_mcnt[head * NR + row];
        float ec = expf(c), eac = expf(LRA * c);
        float wii = (ri < -c) ? eac * expf(LRA * ri) : ec * expf(ri);
        float hid = g_h[(size_t)row * 256 + head * 128 + d];
        float P1m = 0.f, P2m = 0.f, Z1m = 0.f, Z2m = 0.f;
        if (m > 0) {
            size_t off = ((size_t)base + m - 1) * 128 + d;
            P1m = g_P1[off];
            P2m = g_P2[off];
            Z1m = g_Z1[base + m - 1];
            Z2m = g_Z2[base + m - 1];
        }
        float denom = ec * (z1tot - Z1m) + eac * Z2m - wii;
        float numer = ec * (p1tot - P1m) + eac * P2m - wii * hid;
        float o = numer / denom + hid;
        xo[(size_t)row * 256 + head * 128 + d] = (o > 0.f) ? o : expm1f(o);
    }
}

// ---------------- launch ----------------
extern "C" void kernel_launch(void* const* d_in, const int* in_sizes, int n_in,
                              void* d_out, int out_size)
{
    const float* x   = (const float*)d_in[0];
    const float* W00 = (const float*)d_in[2];
    const float* b00 = (const float*)d_in[3];
    const float* a00 = (const float*)d_in[4];
    const float* W01 = (const float*)d_in[5];
    const float* b01 = (const float*)d_in[6];
    const float* a01 = (const float*)d_in[7];
    const float* W10 = (const float*)d_in[8];
    const float* b10 = (const float*)d_in[9];
    const float* a10 = (const float*)d_in[10];
    const float* W11 = (const float*)d_in[11];
    const float* b11 = (const float*)d_in[12];
    const float* a11 = (const float*)d_in[13];
    float* out = (float*)d_out;

    pack_kernel<<<64, 256>>>(W00, b00, a00, W01, b01, a01,
                             W10, b10, a10, W11, b11, a11);

    // layer 0
    gemm_kernel<<<dim3(2, 128), 256>>>(x, 0);
    hlhr_kernel<<<4096, 256>>>(0);
    sort_kernel<<<16, 1024>>>();
    prefix_kernel<<<16, 256>>>();
    msearch_kernel<<<128, 256>>>();
    lookup_kernel<<<dim3(32, 8), 256>>>(nullptr);

    // layer 1
    gemm_kernel<<<dim3(2, 128), 256>>>(nullptr, 1);
    hlhr_kernel<<<4096, 256>>>(1);
    sort_kernel<<<16, 1024>>>();
    prefix_kernel<<<16, 256>>>();
    msearch_kernel<<<128, 256>>>();
    lookup_kernel<<<dim3(32, 8), 256>>>(out);
}

// round 3
// speedup vs baseline: 2.5413x; 2.5413x over previous
#include <cuda_runtime.h>
#include <cstddef>

#define NB 8
#define NN 2048
#define NR 16384          // NB*NN rows
#define LRA 0.2f          // leaky relu slope

typedef unsigned long long ull;

// ---------------- device scratch (static, no allocation) ----------------
__device__ float g_h[NR * 256];        // per-layer h (both heads concatenated)
__device__ float g_xmid[NR * 256];     // layer-0 output / layer-1 input
__device__ float g_Wcat[2][256 * 256]; // [layer][k][head*128+d]
__device__ float g_bcat[2][256];
__device__ float g_aL[2][2][128];
__device__ float g_aR[2][2][128];
__device__ float g_hl[2 * NR];         // [head][row]
__device__ float g_hr[2 * NR];
__device__ float g_rs[2 * NR];         // sorted hr per (head,b)
__device__ int   g_sidx[2 * NR];       // original index of sorted entry
__device__ int   g_mcnt[2 * NR];       // #entries with r < -hl_i
__device__ float g_P1[2 * NR * 128];   // prefix sums of e^{r} * h   [head][b][j][d]
__device__ float g_P2[2 * NR * 128];   // prefix sums of e^{a r} * h
__device__ float g_Z1[2 * NR];
__device__ float g_Z2[2 * NR];
__device__ float g_CS1[16][32][128];   // chunk sums  [hb][chunk][d]
__device__ float g_CS2[16][32][128];
__device__ float g_ZC1[16][32];
__device__ float g_ZC2[16][32];

// ---------------- f32x2 helpers ----------------
__device__ __forceinline__ ull ffma2(ull a, ull b, ull c) {
    ull d;
    asm("fma.rn.f32x2 %0, %1, %2, %3;" : "=l"(d) : "l"(a), "l"(b), "l"(c));
    return d;
}
__device__ __forceinline__ ull pack2(float x, float y) {
    ull d; asm("mov.b64 %0, {%1, %2};" : "=l"(d) : "f"(x), "f"(y)); return d;
}
__device__ __forceinline__ float2 unpack2(ull v) {
    float2 r; asm("mov.b64 {%0, %1}, %2;" : "=f"(r.x), "=f"(r.y) : "l"(v)); return r;
}

// ---------------- pack weights into fused layouts ----------------
__global__ void pack_kernel(
    const float* W00, const float* b00, const float* a00,
    const float* W01, const float* b01, const float* a01,
    const float* W10, const float* b10, const float* a10,
    const float* W11, const float* b11, const float* a11)
{
    const float* Ws[2][2] = {{W00, W01}, {W10, W11}};
    const float* bs[2][2] = {{b00, b01}, {b10, b11}};
    const float* as[2][2] = {{a00, a01}, {a10, a11}};
    int tid = blockIdx.x * blockDim.x + threadIdx.x;
    int nth = gridDim.x * blockDim.x;
    for (int idx = tid; idx < 2 * 256 * 256; idx += nth) {
        int layer = idx >> 16;
        int rem = idx & 0xFFFF;
        int k = rem >> 8, c = rem & 255;
        g_Wcat[layer][rem] = Ws[layer][c >> 7][k * 128 + (c & 127)];
    }
    for (int idx = tid; idx < 2 * 256; idx += nth) {
        int layer = idx >> 8, c = idx & 255;
        g_bcat[layer][c] = bs[layer][c >> 7][c & 127];
    }
    for (int idx = tid; idx < 2 * 2 * 128; idx += nth) {
        int layer = idx >> 8, head = (idx >> 7) & 1, d = idx & 127;
        g_aL[layer][head][d] = as[layer][head][d];
        g_aR[layer][head][d] = as[layer][head][128 + d];
    }
}

// ---------------- fused 2-head GEMM + hl/hr epilogue ----------------
// M=16384, K=256, Ncols=256. 128x128 tiles, 256 threads, 8x8 micro-tile (f32x2).
__global__ __launch_bounds__(256) void gemm_kernel(const float* __restrict__ Xin, int layer)
{
    const float* X = Xin ? Xin : g_xmid;
    __shared__ float As[2][16][132];
    __shared__ float Bs[2][16][128];
    int t = threadIdx.x;
    int tx = t & 15, ty = t >> 4;
    int m0 = blockIdx.y * 128, n0 = blockIdx.x * 128;
    int head = n0 >> 7;
    const float* Wp = g_Wcat[layer];

    ull acc2[8][4];
#pragma unroll
    for (int i = 0; i < 8; i++)
#pragma unroll
        for (int j = 0; j < 4; j++) acc2[i][j] = 0ull;

    // initial load (k-tile 0) into buffer 0
#pragma unroll
    for (int r = 0; r < 2; r++) {
        int qq = t + r * 256;
        int row = qq >> 2, kq = qq & 3;
        float4 v = *(const float4*)(X + (size_t)(m0 + row) * 256 + kq * 4);
        As[0][kq * 4 + 0][row] = v.x;
        As[0][kq * 4 + 1][row] = v.y;
        As[0][kq * 4 + 2][row] = v.z;
        As[0][kq * 4 + 3][row] = v.w;
    }
#pragma unroll
    for (int r = 0; r < 2; r++) {
        int qq = t + r * 256;
        int row = qq >> 5, nq = qq & 31;
        *(float4*)&Bs[0][row][nq * 4] =
            *(const float4*)(Wp + (size_t)row * 256 + n0 + nq * 4);
    }
    __syncthreads();

    for (int kt = 0; kt < 16; kt++) {
        int cur = kt & 1;
        if (kt < 15) {
            int nxt = cur ^ 1;
            int k0 = (kt + 1) * 16;
#pragma unroll
            for (int r = 0; r < 2; r++) {
                int qq = t + r * 256;
                int row = qq >> 2, kq = qq & 3;
                float4 v = *(const float4*)(X + (size_t)(m0 + row) * 256 + k0 + kq * 4);
                As[nxt][kq * 4 + 0][row] = v.x;
                As[nxt][kq * 4 + 1][row] = v.y;
                As[nxt][kq * 4 + 2][row] = v.z;
                As[nxt][kq * 4 + 3][row] = v.w;
            }
#pragma unroll
            for (int r = 0; r < 2; r++) {
                int qq = t + r * 256;
                int row = qq >> 5, nq = qq & 31;
                *(float4*)&Bs[nxt][row][nq * 4] =
                    *(const float4*)(Wp + (size_t)(k0 + row) * 256 + n0 + nq * 4);
            }
        }
#pragma unroll
        for (int kk = 0; kk < 16; kk++) {
            float a8[8];
            *(float4*)&a8[0] = *(const float4*)&As[cur][kk][ty * 8];
            *(float4*)&a8[4] = *(const float4*)&As[cur][kk][ty * 8 + 4];
            ulonglong2 q0 = *(const ulonglong2*)&Bs[cur][kk][tx * 8];
            ulonglong2 q1 = *(const ulonglong2*)&Bs[cur][kk][tx * 8 + 4];
#pragma unroll
            for (int i = 0; i < 8; i++) {
                ull ad = pack2(a8[i], a8[i]);
                acc2[i][0] = ffma2(ad, q0.x, acc2[i][0]);
                acc2[i][1] = ffma2(ad, q0.y, acc2[i][1]);
                acc2[i][2] = ffma2(ad, q1.x, acc2[i][2]);
                acc2[i][3] = ffma2(ad, q1.y, acc2[i][3]);
            }
        }
        __syncthreads();
    }

    // epilogue: bias, store h, and fused hl/hr partial dots
    float4 bia = *(const float4*)&g_bcat[layer][n0 + tx * 8];
    float4 bib = *(const float4*)&g_bcat[layer][n0 + tx * 8 + 4];
    float aL8[8], aR8[8];
    *(float4*)&aL8[0] = *(const float4*)&g_aL[layer][head][tx * 8];
    *(float4*)&aL8[4] = *(const float4*)&g_aL[layer][head][tx * 8 + 4];
    *(float4*)&aR8[0] = *(const float4*)&g_aR[layer][head][tx * 8];
    *(float4*)&aR8[4] = *(const float4*)&g_aR[layer][head][tx * 8 + 4];

    float pl[8], pr[8];
#pragma unroll
    for (int i = 0; i < 8; i++) {
        int row = m0 + ty * 8 + i;
        float2 v0 = unpack2(acc2[i][0]);
        float2 v1 = unpack2(acc2[i][1]);
        float2 v2 = unpack2(acc2[i][2]);
        float2 v3 = unpack2(acc2[i][3]);
        float h0 = v0.x + bia.x, h1 = v0.y + bia.y;
        float h2 = v1.x + bia.z, h3 = v1.y + bia.w;
        float h4 = v2.x + bib.x, h5 = v2.y + bib.y;
        float h6 = v3.x + bib.z, h7 = v3.y + bib.w;
        float4 o0 = {h0, h1, h2, h3};
        float4 o1 = {h4, h5, h6, h7};
        *(float4*)&g_h[(size_t)row * 256 + n0 + tx * 8] = o0;
        *(float4*)&g_h[(size_t)row * 256 + n0 + tx * 8 + 4] = o1;
        float l = h0 * aL8[0] + h1 * aL8[1] + h2 * aL8[2] + h3 * aL8[3]
                + h4 * aL8[4] + h5 * aL8[5] + h6 * aL8[6] + h7 * aL8[7];
        float r = h0 * aR8[0] + h1 * aR8[1] + h2 * aR8[2] + h3 * aR8[3]
                + h4 * aR8[4] + h5 * aR8[5] + h6 * aR8[6] + h7 * aR8[7];
        pl[i] = l; pr[i] = r;
    }
    // reduce over tx (16-lane groups inside each warp)
#pragma unroll
    for (int off = 1; off < 16; off <<= 1) {
#pragma unroll
        for (int i = 0; i < 8; i++) {
            pl[i] += __shfl_xor_sync(0xFFFFFFFFu, pl[i], off);
            pr[i] += __shfl_xor_sync(0xFFFFFFFFu, pr[i], off);
        }
    }
    if (tx == 0) {
#pragma unroll
        for (int i = 0; i < 8; i++) {
            int row = m0 + ty * 8 + i;
            g_hl[head * NR + row] = pl[i];
            g_hr[head * NR + row] = pr[i];
        }
    }
}

// ---------------- bitonic sort of hr per (head,b), packed u64 ----------------
__global__ __launch_bounds__(1024) void sort_kernel()
{
    __shared__ ull kv[2048];
    int hb = blockIdx.x;
    int t = threadIdx.x;
    int base = (hb >> 3) * NR + (hb & 7) * 2048;
    for (int i = t; i < 2048; i += 1024) {
        unsigned u = __float_as_uint(g_hr[base + i]);
        u ^= (u >> 31) ? 0xFFFFFFFFu : 0x80000000u;   // sortable uint
        kv[i] = ((ull)u << 32) | (unsigned)i;
    }
    __syncthreads();
    for (int k = 2; k <= 2048; k <<= 1) {
        for (int j = k >> 1; j > 0; j >>= 1) {
            for (int i = t; i < 2048; i += 1024) {
                int ixj = i ^ j;
                if (ixj > i) {
                    bool up = ((i & k) == 0);
                    ull a = kv[i], b = kv[ixj];
                    if ((a > b) == up) { kv[i] = b; kv[ixj] = a; }
                }
            }
            __syncthreads();
        }
    }
    for (int i = t; i < 2048; i += 1024) {
        unsigned u = (unsigned)(kv[i] >> 32);
        u ^= (u >> 31) ? 0x80000000u : 0xFFFFFFFFu;
        g_rs[base + i] = __uint_as_float(u);
        g_sidx[base + i] = (int)(kv[i] & 0xFFFFFFFFu);
    }
}

// ---------------- threshold binary search per (head,row) ----------------
__global__ __launch_bounds__(256) void msearch_kernel()
{
    int idx = blockIdx.x * blockDim.x + threadIdx.x;
    if (idx >= 2 * NR) return;
    int head = idx >> 14, row = idx & (NR - 1);
    int b = row >> 11;
    float thr = -g_hl[head * NR + row];
    const float* rs = &g_rs[head * NR + b * 2048];
    int lo = 0, hi = 2048;
    while (lo < hi) {
        int mid = (lo + hi) >> 1;
        if (rs[mid] < thr) lo = mid + 1; else hi = mid;
    }
    g_mcnt[idx] = lo;
}

// ---------------- chunked prefix: pass A = per-chunk sums ----------------
// grid 512: blk = hb*32 + chunk; 256 threads (t<128 -> P1 half, else P2)
__global__ __launch_bounds__(256) void prefixA_kernel()
{
    __shared__ float ew1[64], ew2[64];
    __shared__ int   sid[64];
    int blk = blockIdx.x;
    int hb = blk >> 5, chunk = blk & 31;
    int head = hb >> 3, b = hb & 7;
    int base = head * NR + b * 2048;
    int j0 = chunk * 64;
    int t = threadIdx.x;
    if (t < 64) {
        float r = g_rs[base + j0 + t];
        ew1[t] = expf(r);
        ew2[t] = expf(LRA * r);
        sid[t] = g_sidx[base + j0 + t];
    }
    __syncthreads();
    int d = t & 127;
    bool a2 = (t >= 128);
    const float* ew = a2 ? ew2 : ew1;
    const float* hp = g_h + (size_t)(b * 2048) * 256 + head * 128 + d;
    float acc = 0.f, z = 0.f;
#pragma unroll 4
    for (int j = 0; j < 64; j++) {
        float v = __ldg(hp + (size_t)sid[j] * 256);
        acc = fmaf(ew[j], v, acc);
        if (d == 0) z += ew[j];
    }
    (a2 ? g_CS2 : g_CS1)[hb][chunk][d] = acc;
    if (d == 0) (a2 ? g_ZC2 : g_ZC1)[hb][chunk] = z;
}

// ---------------- chunked prefix: pass C = write full prefixes ----------------
__global__ __launch_bounds__(256) void prefixC_kernel()
{
    __shared__ float ew1[64], ew2[64];
    __shared__ int   sid[64];
    int blk = blockIdx.x;
    int hb = blk >> 5, chunk = blk & 31;
    int head = hb >> 3, b = hb & 7;
    int base = head * NR + b * 2048;
    int j0 = chunk * 64;
    int t = threadIdx.x;
    if (t < 64) {
        float r = g_rs[base + j0 + t];
        ew1[t] = expf(r);
        ew2[t] = expf(LRA * r);
        sid[t] = g_sidx[base + j0 + t];
    }
    __syncthreads();
    int d = t & 127;
    bool a2 = (t >= 128);
    const float* ew = a2 ? ew2 : ew1;
    const float* hp = g_h + (size_t)(b * 2048) * 256 + head * 128 + d;
    float acc = 0.f, z = 0.f;
    {
        const float* CS = a2 ? &g_CS2[hb][0][0] : &g_CS1[hb][0][0];
        const float* ZC = a2 ? &g_ZC2[hb][0]    : &g_ZC1[hb][0];
        for (int c = 0; c < chunk; c++) {
            acc += CS[c * 128 + d];
            if (d == 0) z += ZC[c];
        }
    }
    float* P = (a2 ? g_P2 : g_P1) + (size_t)base * 128 + d;
    float* Z = (a2 ? g_Z2 : g_Z1) + base;
#pragma unroll 4
    for (int j = 0; j < 64; j++) {
        float v = __ldg(hp + (size_t)sid[j] * 256);
        acc = fmaf(ew[j], v, acc);
        P[(size_t)(j0 + j) * 128] = acc;
        if (d == 0) { z += ew[j]; Z[j0 + j] = z; }
    }
}

// ---------------- per-node O(D) lookup + ELU ----------------
__global__ __launch_bounds__(256) void lookup_kernel(float* xout)
{
    float* xo = xout ? xout : g_xmid;
    int b = blockIdx.y;
    int n0 = blockIdx.x * 16;
    int t = threadIdx.x;
    int head = t >> 7, d = t & 127;
    int base = head * NR + b * 2048;
    float p1tot = g_P1[((size_t)base + 2047) * 128 + d];
    float z1tot = g_Z1[base + 2047];
    for (int nn = 0; nn < 16; nn++) {
        int row = b * 2048 + n0 + nn;
        float c = g_hl[head * NR + row];
        float ri = g_hr[head * NR + row];
        int m = g_mcnt[head * NR + row];
        float ec = expf(c), eac = expf(LRA * c);
        float wii = (ri < -c) ? eac * expf(LRA * ri) : ec * expf(ri);
        float hid = g_h[(size_t)row * 256 + head * 128 + d];
        float P1m = 0.f, P2m = 0.f, Z1m = 0.f, Z2m = 0.f;
        if (m > 0) {
            size_t off = ((size_t)base + m - 1) * 128 + d;
            P1m = g_P1[off];
            P2m = g_P2[off];
            Z1m = g_Z1[base + m - 1];
            Z2m = g_Z2[base + m - 1];
        }
        float denom = ec * (z1tot - Z1m) + eac * Z2m - wii;
        float numer = ec * (p1tot - P1m) + eac * P2m - wii * hid;
        float o = numer / denom + hid;
        xo[(size_t)row * 256 + head * 128 + d] = (o > 0.f) ? o : expm1f(o);
    }
}

// ---------------- launch ----------------
extern "C" void kernel_launch(void* const* d_in, const int* in_sizes, int n_in,
                              void* d_out, int out_size)
{
    const float* x   = (const float*)d_in[0];
    const float* W00 = (const float*)d_in[2];
    const float* b00 = (const float*)d_in[3];
    const float* a00 = (const float*)d_in[4];
    const float* W01 = (const float*)d_in[5];
    const float* b01 = (const float*)d_in[6];
    const float* a01 = (const float*)d_in[7];
    const float* W10 = (const float*)d_in[8];
    const float* b10 = (const float*)d_in[9];
    const float* a10 = (const float*)d_in[10];
    const float* W11 = (const float*)d_in[11];
    const float* b11 = (const float*)d_in[12];
    const float* a11 = (const float*)d_in[13];
    float* out = (float*)d_out;

    pack_kernel<<<64, 256>>>(W00, b00, a00, W01, b01, a01,
                             W10, b10, a10, W11, b11, a11);

    // layer 0
    gemm_kernel<<<dim3(2, 128), 256>>>(x, 0);
    sort_kernel<<<16, 1024>>>();
    prefixA_kernel<<<512, 256>>>();
    prefixC_kernel<<<512, 256>>>();
    msearch_kernel<<<128, 256>>>();
    lookup_kernel<<<dim3(128, 8), 256>>>(nullptr);

    // layer 1
    gemm_kernel<<<dim3(2, 128), 256>>>(nullptr, 1);
    sort_kernel<<<16, 1024>>>();
    prefixA_kernel<<<512, 256>>>();
    prefixC_kernel<<<512, 256>>>();
    msearch_kernel<<<128, 256>>>();
    lookup_kernel<<<dim3(128, 8), 256>>>(out);
}

// round 6
// speedup vs baseline: 3.2812x; 1.2911x over previous
#include <cuda_runtime.h>
#include <cuda_bf16.h>
#include <cstddef>
#include <cstdint>

#define NB 8
#define NN 2048
#define NR 16384          // NB*NN rows
#define LRA 0.2f

typedef unsigned long long ull;

// ---------------- device scratch ----------------
__device__ float g_h[NR * 256];
__device__ float g_xmid[NR * 256];
__device__ float g_WT[2][256 * 256];   // [layer][n][k]  (B operand, K-major)
__device__ float g_bcat[2][256];
__device__ float g_aL[2][2][128];
__device__ float g_aR[2][2][128];
__device__ float g_hl[2 * NR];
__device__ float g_hr[2 * NR];
__device__ float g_rs[2 * NR];
__device__ int   g_sidx[2 * NR];
__device__ float g_P1[2 * NR * 128];
__device__ float g_P2[2 * NR * 128];
__device__ float g_Z1[2 * NR];
__device__ float g_Z2[2 * NR];
__device__ float g_CS1[16][32][128];
__device__ float g_CS2[16][32][128];
__device__ float g_ZC1[16][32];
__device__ float g_ZC2[16][32];

// ---------------- helpers ----------------
__device__ __forceinline__ uint32_t smem_u32(const void* p) {
    uint32_t a;
    asm("{ .reg .u64 tmp; cvta.to.shared.u64 tmp, %1; cvt.u32.u64 %0, tmp; }"
        : "=r"(a) : "l"(p));
    return a;
}
__device__ __forceinline__ void ldmx4(uint32_t* r, uint32_t addr) {
    asm volatile("ldmatrix.sync.aligned.m8n8.x4.shared.b16 {%0,%1,%2,%3}, [%4];"
        : "=r"(r[0]), "=r"(r[1]), "=r"(r[2]), "=r"(r[3]) : "r"(addr));
}
__device__ __forceinline__ void ldmx2(uint32_t* r, uint32_t addr) {
    asm volatile("ldmatrix.sync.aligned.m8n8.x2.shared.b16 {%0,%1}, [%2];"
        : "=r"(r[0]), "=r"(r[1]) : "r"(addr));
}
__device__ __forceinline__ void mma_bf16(float* c, const uint32_t* a, const uint32_t* b) {
    asm volatile("mma.sync.aligned.m16n8k16.row.col.f32.bf16.bf16.f32 "
        "{%0,%1,%2,%3}, {%4,%5,%6,%7}, {%8,%9}, {%0,%1,%2,%3};"
        : "+f"(c[0]), "+f"(c[1]), "+f"(c[2]), "+f"(c[3])
        : "r"(a[0]), "r"(a[1]), "r"(a[2]), "r"(a[3]), "r"(b[0]), "r"(b[1]));
}

// bf16 hi/lo split of a float4 -> two 8B packets
__device__ __forceinline__ void cvt_hilo(float4 v, uint2& hi, uint2& lo) {
    __nv_bfloat16 h0 = __float2bfloat16(v.x), h1 = __float2bfloat16(v.y);
    __nv_bfloat16 h2 = __float2bfloat16(v.z), h3 = __float2bfloat16(v.w);
    __nv_bfloat16 l0 = __float2bfloat16(v.x - __bfloat162float(h0));
    __nv_bfloat16 l1 = __float2bfloat16(v.y - __bfloat162float(h1));
    __nv_bfloat16 l2 = __float2bfloat16(v.z - __bfloat162float(h2));
    __nv_bfloat16 l3 = __float2bfloat16(v.w - __bfloat162float(h3));
    hi.x = ((uint32_t)__bfloat16_as_ushort(h1) << 16) | __bfloat16_as_ushort(h0);
    hi.y = ((uint32_t)__bfloat16_as_ushort(h3) << 16) | __bfloat16_as_ushort(h2);
    lo.x = ((uint32_t)__bfloat16_as_ushort(l1) << 16) | __bfloat16_as_ushort(l0);
    lo.y = ((uint32_t)__bfloat16_as_ushort(l3) << 16) | __bfloat16_as_ushort(l2);
}

// ---------------- pack: W -> WT (K-major B operand), bias, a vectors --------
__global__ void pack_kernel(
    const float* W00, const float* b00, const float* a00,
    const float* W01, const float* b01, const float* a01,
    const float* W10, const float* b10, const float* a10,
    const float* W11, const float* b11, const float* a11)
{
    const float* Ws[2][2] = {{W00, W01}, {W10, W11}};
    const float* bs[2][2] = {{b00, b01}, {b10, b11}};
    const float* as[2][2] = {{a00, a01}, {a10, a11}};
    int tid = blockIdx.x * blockDim.x + threadIdx.x;
    int nth = gridDim.x * blockDim.x;
    for (int idx = tid; idx < 2 * 256 * 256; idx += nth) {
        int layer = idx >> 16;
        int rem = idx & 0xFFFF;
        int n = rem >> 8, k = rem & 255;
        g_WT[layer][rem] = Ws[layer][n >> 7][k * 128 + (n & 127)];
    }
    for (int idx = tid; idx < 2 * 256; idx += nth) {
        int layer = idx >> 8, c = idx & 255;
        g_bcat[layer][c] = bs[layer][c >> 7][c & 127];
    }
    for (int idx = tid; idx < 2 * 2 * 128; idx += nth) {
        int layer = idx >> 8, head = (idx >> 7) & 1, d = idx & 127;
        g_aL[layer][head][d] = as[layer][head][d];
        g_aR[layer][head][d] = as[layer][head][128 + d];
    }
}

// ---------------- HMMA GEMM: h = X @ W + b  (3-pass bf16 hi/lo split) --------
// grid (2, 128), 256 threads. Block tile M=128 x N=128 (one head per bx).
// Warp grid 4x2 (wm: 32 rows, wn: 64 cols). mma m16n8k16.
__global__ __launch_bounds__(256) void gemm_mma_kernel(const float* __restrict__ Xin, int layer)
{
    __shared__ __align__(16) __nv_bfloat16 sA[2][128][40]; // [hi/lo][row][k(32)+pad8]
    __shared__ __align__(16) __nv_bfloat16 sB[2][128][40];
    const float* X = Xin ? Xin : g_xmid;
    int t = threadIdx.x, lane = t & 31, wid = t >> 5;
    int wm = wid & 3, wn = wid >> 2;
    int m0 = blockIdx.y * 128, n0 = blockIdx.x * 128;
    const float* Wp = g_WT[layer] + (size_t)n0 * 256;

    float acc[2][8][4];
#pragma unroll
    for (int mi = 0; mi < 2; mi++)
#pragma unroll
        for (int ni = 0; ni < 8; ni++)
#pragma unroll
            for (int q = 0; q < 4; q++) acc[mi][ni][q] = 0.f;

    uint32_t baseA0 = smem_u32(&sA[0][0][0]);
    uint32_t baseA1 = smem_u32(&sA[1][0][0]);
    uint32_t baseB0 = smem_u32(&sB[0][0][0]);
    uint32_t baseB1 = smem_u32(&sB[1][0][0]);

    // ldmatrix lane-address mapping (FIXED):
    // A x4: lanes 0-7 -> (row, k0); 8-15 -> (row+8, k0); 16-23 -> (row, k8); 24-31 -> (row+8, k8)
    int arow = wm * 32 + (lane & 7) + (lane & 8);          // + mi*16
    int acolx = (lane & 16) >> 1;                           // + ks
    // B x2: lanes 0-7 -> (n, k0); 8-15 -> (n, k8)
    int brow = wn * 64 + (lane & 7);                        // + ni*8
    int bcolx = (lane & 8);                                 // + ks

    for (int kt = 0; kt < 8; kt++) {
        int k0 = kt * 32;
#pragma unroll
        for (int it = 0; it < 4; it++) {
            int idx = t + it * 256;
            int row = idx >> 3, kq = idx & 7;
            float4 v = *(const float4*)(X + (size_t)(m0 + row) * 256 + k0 + kq * 4);
            uint2 hi, lo;
            cvt_hilo(v, hi, lo);
            *(uint2*)&sA[0][row][kq * 4] = hi;
            *(uint2*)&sA[1][row][kq * 4] = lo;
            float4 w = *(const float4*)(Wp + (size_t)row * 256 + k0 + kq * 4);
            cvt_hilo(w, hi, lo);
            *(uint2*)&sB[0][row][kq * 4] = hi;
            *(uint2*)&sB[1][row][kq * 4] = lo;
        }
        __syncthreads();
#pragma unroll
        for (int ks = 0; ks < 32; ks += 16) {
            uint32_t ah[2][4], al[2][4], bh[8][2], bl[8][2];
#pragma unroll
            for (int mi = 0; mi < 2; mi++) {
                uint32_t off = (uint32_t)((arow + mi * 16) * 40 + ks + acolx) * 2;
                ldmx4(ah[mi], baseA0 + off);
                ldmx4(al[mi], baseA1 + off);
            }
#pragma unroll
            for (int ni = 0; ni < 8; ni++) {
                uint32_t off = (uint32_t)((brow + ni * 8) * 40 + ks + bcolx) * 2;
                ldmx2(bh[ni], baseB0 + off);
                ldmx2(bl[ni], baseB1 + off);
            }
#pragma unroll
            for (int mi = 0; mi < 2; mi++)
#pragma unroll
                for (int ni = 0; ni < 8; ni++) {
                    mma_bf16(acc[mi][ni], ah[mi], bh[ni]);
                    mma_bf16(acc[mi][ni], ah[mi], bl[ni]);
                    mma_bf16(acc[mi][ni], al[mi], bh[ni]);
                }
        }
        __syncthreads();
    }

    // epilogue: D fragment -> g_h with bias
    int rbase = m0 + wm * 32 + (lane >> 2);
    int cb = n0 + wn * 64 + (lane & 3) * 2;
#pragma unroll
    for (int mi = 0; mi < 2; mi++)
#pragma unroll
        for (int ni = 0; ni < 8; ni++) {
            int gc = cb + ni * 8;
            float b0v = g_bcat[layer][gc], b1v = g_bcat[layer][gc + 1];
            int gr = rbase + mi * 16;
            float2 p0 = {acc[mi][ni][0] + b0v, acc[mi][ni][1] + b1v};
            float2 p1 = {acc[mi][ni][2] + b0v, acc[mi][ni][3] + b1v};
            *(float2*)&g_h[(size_t)gr * 256 + gc] = p0;
            *(float2*)&g_h[(size_t)(gr + 8) * 256 + gc] = p1;
        }
}

// ---------------- hl = h . a_l, hr = h . a_r (one warp per row,head) ---------
__global__ __launch_bounds__(256) void hlhr_kernel(int layer)
{
    int t = threadIdx.x;
    int warp = (blockIdx.x << 3) + (t >> 5);
    int lane = t & 31;
    int head = warp & 1, row = warp >> 1;
    float4 hv = *(const float4*)&g_h[(size_t)row * 256 + head * 128 + lane * 4];
    float4 al = *(const float4*)&g_aL[layer][head][lane * 4];
    float4 ar = *(const float4*)&g_aR[layer][head][lane * 4];
    float sl = hv.x * al.x + hv.y * al.y + hv.z * al.z + hv.w * al.w;
    float sr = hv.x * ar.x + hv.y * ar.y + hv.z * ar.z + hv.w * ar.w;
#pragma unroll
    for (int o = 16; o > 0; o >>= 1) {
        sl += __shfl_xor_sync(0xFFFFFFFFu, sl, o);
        sr += __shfl_xor_sync(0xFFFFFFFFu, sr, o);
    }
    if (lane == 0) {
        g_hl[head * NR + row] = sl;
        g_hr[head * NR + row] = sr;
    }
}

// ---------------- bitonic sort with warp-register tails ----------------
__device__ __forceinline__ ull bswap_reg(ull v, int j, bool up, int i) {
    ull pv = __shfl_xor_sync(0xFFFFFFFFu, v, j);
    bool lower = ((i & j) == 0);
    return (lower == up) ? (v < pv ? v : pv) : (v > pv ? v : pv);
}

__global__ __launch_bounds__(1024) void sort_kernel()
{
    __shared__ ull kv[2048];
    int hb = blockIdx.x;
    int t = threadIdx.x;
    int base = (hb >> 3) * NR + (hb & 7) * 2048;

    auto mkkey = [](float f, int i) -> ull {
        unsigned u = __float_as_uint(f);
        u ^= (u >> 31) ? 0xFFFFFFFFu : 0x80000000u;
        return ((ull)u << 32) | (unsigned)i;
    };
    ull v1 = mkkey(g_hr[base + t], t);
    ull v2 = mkkey(g_hr[base + t + 1024], t + 1024);

#pragma unroll
    for (int k = 2; k <= 32; k <<= 1) {
        bool up1 = ((t & k) == 0);
        bool up2 = (((t + 1024) & k) == 0);
        for (int j = k >> 1; j >= 1; j >>= 1) {
            v1 = bswap_reg(v1, j, up1, t);
            v2 = bswap_reg(v2, j, up2, t + 1024);
        }
    }
    kv[t] = v1; kv[t + 1024] = v2;
    __syncthreads();

    for (int k = 64; k <= 2048; k <<= 1) {
        for (int j = k >> 1; j >= 32; j >>= 1) {
#pragma unroll
            for (int q = 0; q < 2; q++) {
                int i = t + q * 1024;
                int ixj = i ^ j;
                if (ixj > i) {
                    bool up = ((i & k) == 0);
                    ull a = kv[i], b = kv[ixj];
                    if ((a > b) == up) { kv[i] = b; kv[ixj] = a; }
                }
            }
            __syncthreads();
        }
        v1 = kv[t]; v2 = kv[t + 1024];
        bool up1 = ((t & k) == 0);
        bool up2 = (((t + 1024) & k) == 0);
        for (int j = 16; j >= 1; j >>= 1) {
            v1 = bswap_reg(v1, j, up1, t);
            v2 = bswap_reg(v2, j, up2, t + 1024);
        }
        if (k < 2048) { kv[t] = v1; kv[t + 1024] = v2; __syncthreads(); }
    }

    auto unkey = [](ull v, float* f, int* idx) {
        unsigned u = (unsigned)(v >> 32);
        u ^= (u >> 31) ? 0x80000000u : 0xFFFFFFFFu;
        *f = __uint_as_float(u);
        *idx = (int)(v & 0xFFFFFFFFu);
    };
    float f; int idx;
    unkey(v1, &f, &idx); g_rs[base + t] = f;        g_sidx[base + t] = idx;
    unkey(v2, &f, &idx); g_rs[base + t + 1024] = f; g_sidx[base + t + 1024] = idx;
}

// ---------------- chunked prefix pass A: per-chunk sums (single gather) ------
__global__ __launch_bounds__(256) void prefixA_kernel()
{
    __shared__ float ew1[2][64], ew2[2][64];
    __shared__ int   sid[2][64];
    int blk = blockIdx.x;
    int hb = blk >> 4, pair = blk & 15;
    int head = hb >> 3, b = hb & 7;
    int base = head * NR + b * 2048;
    int t = threadIdx.x;
    if (t < 128) {
        int ch = t >> 6, jj = t & 63;
        float r = g_rs[base + (2 * pair + ch) * 64 + jj];
        ew1[ch][jj] = expf(r);
        ew2[ch][jj] = expf(LRA * r);
        sid[ch][jj] = g_sidx[base + (2 * pair + ch) * 64 + jj];
    }
    __syncthreads();
    int half = t >> 7, d = t & 127;
    int chunk = 2 * pair + half;
    const float* hp = g_h + (size_t)(b * 2048) * 256 + head * 128 + d;
    float a1 = 0.f, a2 = 0.f, z1 = 0.f, z2 = 0.f;
#pragma unroll 4
    for (int j = 0; j < 64; j++) {
        float v = __ldg(hp + (size_t)sid[half][j] * 256);
        float w1 = ew1[half][j], w2 = ew2[half][j];
        a1 = fmaf(w1, v, a1);
        a2 = fmaf(w2, v, a2);
        if (d == 0) { z1 += w1; z2 += w2; }
    }
    g_CS1[hb][chunk][d] = a1;
    g_CS2[hb][chunk][d] = a2;
    if (d == 0) { g_ZC1[hb][chunk] = z1; g_ZC2[hb][chunk] = z2; }
}

// ---------------- chunked prefix pass C: write full prefixes -----------------
__global__ __launch_bounds__(256) void prefixC_kernel()
{
    __shared__ float ew1[2][64], ew2[2][64];
    __shared__ int   sid[2][64];
    int blk = blockIdx.x;
    int hb = blk >> 4, pair = blk & 15;
    int head = hb >> 3, b = hb & 7;
    int base = head * NR + b * 2048;
    int t = threadIdx.x;
    if (t < 128) {
        int ch = t >> 6, jj = t & 63;
        float r = g_rs[base + (2 * pair + ch) * 64 + jj];
        ew1[ch][jj] = expf(r);
        ew2[ch][jj] = expf(LRA * r);
        sid[ch][jj] = g_sidx[base + (2 * pair + ch) * 64 + jj];
    }
    __syncthreads();
    int half = t >> 7, d = t & 127;
    int chunk = 2 * pair + half;
    int j0 = chunk * 64;
    const float* hp = g_h + (size_t)(b * 2048) * 256 + head * 128 + d;
    float a1 = 0.f, a2 = 0.f, z1 = 0.f, z2 = 0.f;
    for (int c = 0; c < chunk; c++) {
        a1 += g_CS1[hb][c][d];
        a2 += g_CS2[hb][c][d];
        if (d == 0) { z1 += g_ZC1[hb][c]; z2 += g_ZC2[hb][c]; }
    }
    float* P1 = g_P1 + (size_t)base * 128 + d;
    float* P2 = g_P2 + (size_t)base * 128 + d;
#pragma unroll 4
    for (int j = 0; j < 64; j++) {
        float v = __ldg(hp + (size_t)sid[half][j] * 256);
        float w1 = ew1[half][j], w2 = ew2[half][j];
        a1 = fmaf(w1, v, a1);
        a2 = fmaf(w2, v, a2);
        P1[(size_t)(j0 + j) * 128] = a1;
        P2[(size_t)(j0 + j) * 128] = a2;
        if (d == 0) {
            z1 += w1; z2 += w2;
            g_Z1[base + j0 + j] = z1;
            g_Z2[base + j0 + j] = z2;
        }
    }
}

// ---------------- per-node O(D) lookup + ELU (shared binary search) ----------
__global__ __launch_bounds__(256) void lookup_kernel(float* xout)
{
    __shared__ int sm[2][16];
    float* xo = xout ? xout : g_xmid;
    int b = blockIdx.y;
    int n0 = blockIdx.x * 16;
    int t = threadIdx.x;
    if (t < 32) {
        int hh = t >> 4, nn = t & 15;
        int bb = hh * NR + b * 2048;
        float thr = -g_hl[hh * NR + b * 2048 + n0 + nn];
        const float* rs = &g_rs[bb];
        int lo = 0, hi = 2048;
        while (lo < hi) {
            int mid = (lo + hi) >> 1;
            if (rs[mid] < thr) lo = mid + 1; else hi = mid;
        }
        sm[hh][nn] = lo;
    }
    __syncthreads();
    int head = t >> 7, d = t & 127;
    int base = head * NR + b * 2048;
    float p1tot = g_P1[((size_t)base + 2047) * 128 + d];
    float z1tot = g_Z1[base + 2047];
    for (int nn = 0; nn < 16; nn++) {
        int row = b * 2048 + n0 + nn;
        float c = g_hl[head * NR + row];
        float ri = g_hr[head * NR + row];
        int m = sm[head][nn];
        float ec = expf(c), eac = expf(LRA * c);
        float wii = (ri < -c) ? eac * expf(LRA * ri) : ec * expf(ri);
        float hid = g_h[(size_t)row * 256 + head * 128 + d];
        float P1m = 0.f, P2m = 0.f, Z1m = 0.f, Z2m = 0.f;
        if (m > 0) {
            size_t off = ((size_t)base + m - 1) * 128 + d;
            P1m = g_P1[off];
            P2m = g_P2[off];
            Z1m = g_Z1[base + m - 1];
            Z2m = g_Z2[base + m - 1];
        }
        float denom = ec * (z1tot - Z1m) + eac * Z2m - wii;
        float numer = ec * (p1tot - P1m) + eac * P2m - wii * hid;
        float o = numer / denom + hid;
        xo[(size_t)row * 256 + head * 128 + d] = (o > 0.f) ? o : expm1f(o);
    }
}

// ---------------- launch ----------------
extern "C" void kernel_launch(void* const* d_in, const int* in_sizes, int n_in,
                              void* d_out, int out_size)
{
    const float* x   = (const float*)d_in[0];
    const float* W00 = (const float*)d_in[2];
    const float* b00 = (const float*)d_in[3];
    const float* a00 = (const float*)d_in[4];
    const float* W01 = (const float*)d_in[5];
    const float* b01 = (const float*)d_in[6];
    const float* a01 = (const float*)d_in[7];
    const float* W10 = (const float*)d_in[8];
    const float* b10 = (const float*)d_in[9];
    const float* a10 = (const float*)d_in[10];
    const float* W11 = (const float*)d_in[11];
    const float* b11 = (const float*)d_in[12];
    const float* a11 = (const float*)d_in[13];
    float* out = (float*)d_out;

    pack_kernel<<<64, 256>>>(W00, b00, a00, W01, b01, a01,
                             W10, b10, a10, W11, b11, a11);

    // layer 0
    gemm_mma_kernel<<<dim3(2, 128), 256>>>(x, 0);
    hlhr_kernel<<<4096, 256>>>(0);
    sort_kernel<<<16, 1024>>>();
    prefixA_kernel<<<256, 256>>>();
    prefixC_kernel<<<256, 256>>>();
    lookup_kernel<<<dim3(128, 8), 256>>>(nullptr);

    // layer 1
    gemm_mma_kernel<<<dim3(2, 128), 256>>>(nullptr, 1);
    hlhr_kernel<<<4096, 256>>>(1);
    sort_kernel<<<16, 1024>>>();
    prefixA_kernel<<<256, 256>>>();
    prefixC_kernel<<<256, 256>>>();
    lookup_kernel<<<dim3(128, 8), 256>>>(out);
}

// round 7
// speedup vs baseline: 3.3148x; 1.0102x over previous
#include <cuda_runtime.h>
#include <cuda_bf16.h>
#include <cstddef>
#include <cstdint>

#define NB 8
#define NN 2048
#define NR 16384          // NB*NN rows
#define LRA 0.2f

typedef unsigned long long ull;

// ---------------- device scratch ----------------
__device__ float g_h[NR * 256];
__device__ float g_xmid[NR * 256];
__device__ float g_WT[2][256 * 256];   // [layer][n][k]  (B operand, K-major)
__device__ float g_bcat[2][256];
__device__ float g_aL[2][2][128];
__device__ float g_aR[2][2][128];
__device__ float g_hl[2 * NR];
__device__ float g_hr[2 * NR];
__device__ float g_rs[2 * NR];
__device__ int   g_sidx[2 * NR];
__device__ float g_P1[2 * NR * 128];
__device__ float g_P2[2 * NR * 128];
__device__ float g_Z1[2 * NR];
__device__ float g_Z2[2 * NR];
__device__ float g_CS1[16][32][128];
__device__ float g_CS2[16][32][128];
__device__ float g_ZC1[16][32];
__device__ float g_ZC2[16][32];

// ---------------- helpers ----------------
__device__ __forceinline__ uint32_t smem_u32(const void* p) {
    uint32_t a;
    asm("{ .reg .u64 tmp; cvta.to.shared.u64 tmp, %1; cvt.u32.u64 %0, tmp; }"
        : "=r"(a) : "l"(p));
    return a;
}
__device__ __forceinline__ void ldmx4(uint32_t* r, uint32_t addr) {
    asm volatile("ldmatrix.sync.aligned.m8n8.x4.shared.b16 {%0,%1,%2,%3}, [%4];"
        : "=r"(r[0]), "=r"(r[1]), "=r"(r[2]), "=r"(r[3]) : "r"(addr));
}
__device__ __forceinline__ void mma_bf16(float* c, const uint32_t* a, const uint32_t* b) {
    asm volatile("mma.sync.aligned.m16n8k16.row.col.f32.bf16.bf16.f32 "
        "{%0,%1,%2,%3}, {%4,%5,%6,%7}, {%8,%9}, {%0,%1,%2,%3};"
        : "+f"(c[0]), "+f"(c[1]), "+f"(c[2]), "+f"(c[3])
        : "r"(a[0]), "r"(a[1]), "r"(a[2]), "r"(a[3]), "r"(b[0]), "r"(b[1]));
}

// bf16 hi/lo split of a float4 -> two 8B packets
__device__ __forceinline__ void cvt_hilo(float4 v, uint2& hi, uint2& lo) {
    __nv_bfloat16 h0 = __float2bfloat16(v.x), h1 = __float2bfloat16(v.y);
    __nv_bfloat16 h2 = __float2bfloat16(v.z), h3 = __float2bfloat16(v.w);
    __nv_bfloat16 l0 = __float2bfloat16(v.x - __bfloat162float(h0));
    __nv_bfloat16 l1 = __float2bfloat16(v.y - __bfloat162float(h1));
    __nv_bfloat16 l2 = __float2bfloat16(v.z - __bfloat162float(h2));
    __nv_bfloat16 l3 = __float2bfloat16(v.w - __bfloat162float(h3));
    hi.x = ((uint32_t)__bfloat16_as_ushort(h1) << 16) | __bfloat16_as_ushort(h0);
    hi.y = ((uint32_t)__bfloat16_as_ushort(h3) << 16) | __bfloat16_as_ushort(h2);
    lo.x = ((uint32_t)__bfloat16_as_ushort(l1) << 16) | __bfloat16_as_ushort(l0);
    lo.y = ((uint32_t)__bfloat16_as_ushort(l3) << 16) | __bfloat16_as_ushort(l2);
}

// ---------------- pack: W -> WT (K-major B operand), bias, a vectors --------
__global__ void pack_kernel(
    const float* W00, const float* b00, const float* a00,
    const float* W01, const float* b01, const float* a01,
    const float* W10, const float* b10, const float* a10,
    const float* W11, const float* b11, const float* a11)
{
    const float* Ws[2][2] = {{W00, W01}, {W10, W11}};
    const float* bs[2][2] = {{b00, b01}, {b10, b11}};
    const float* as[2][2] = {{a00, a01}, {a10, a11}};
    int tid = blockIdx.x * blockDim.x + threadIdx.x;
    int nth = gridDim.x * blockDim.x;
    for (int idx = tid; idx < 2 * 256 * 256; idx += nth) {
        int layer = idx >> 16;
        int rem = idx & 0xFFFF;
        int n = rem >> 8, k = rem & 255;
        g_WT[layer][rem] = Ws[layer][n >> 7][k * 128 + (n & 127)];
    }
    for (int idx = tid; idx < 2 * 256; idx += nth) {
        int layer = idx >> 8, c = idx & 255;
        g_bcat[layer][c] = bs[layer][c >> 7][c & 127];
    }
    for (int idx = tid; idx < 2 * 2 * 128; idx += nth) {
        int layer = idx >> 8, head = (idx >> 7) & 1, d = idx & 127;
        g_aL[layer][head][d] = as[layer][head][d];
        g_aR[layer][head][d] = as[layer][head][128 + d];
    }
}

// ---------------- HMMA GEMM: h = X @ W + b  (3-pass bf16 hi/lo split) --------
// grid (2, 128), 256 threads. Block tile M=128 x N=128 (one head per bx).
// Warp grid 4x2 (wm: 32 rows, wn: 64 cols). mma m16n8k16.
// Fused epilogue: hl/hr dots (block tile spans a full head).
__global__ __launch_bounds__(256) void gemm_mma_kernel(const float* __restrict__ Xin, int layer)
{
    __shared__ __align__(16) __nv_bfloat16 sA[2][128][40]; // [hi/lo][row][k(32)+pad8]
    __shared__ __align__(16) __nv_bfloat16 sB[2][128][40];
    __shared__ float sHL[128][2], sHR[128][2];
    const float* X = Xin ? Xin : g_xmid;
    int t = threadIdx.x, lane = t & 31, wid = t >> 5;
    int wm = wid & 3, wn = wid >> 2;
    int m0 = blockIdx.y * 128, n0 = blockIdx.x * 128;
    int head = n0 >> 7;
    const float* Wp = g_WT[layer] + (size_t)n0 * 256;

    float acc[2][8][4];
#pragma unroll
    for (int mi = 0; mi < 2; mi++)
#pragma unroll
        for (int ni = 0; ni < 8; ni++)
#pragma unroll
            for (int q = 0; q < 4; q++) acc[mi][ni][q] = 0.f;

    uint32_t baseA0 = smem_u32(&sA[0][0][0]);
    uint32_t baseA1 = smem_u32(&sA[1][0][0]);
    uint32_t baseB0 = smem_u32(&sB[0][0][0]);
    uint32_t baseB1 = smem_u32(&sB[1][0][0]);

    // A x4: lanes 0-7 -> (row, k0); 8-15 -> (row+8, k0); 16-23 -> (row, k8); 24-31 -> (row+8, k8)
    int arow = wm * 32 + (lane & 7) + (lane & 8);          // + mi*16
    int acolx = (lane & 16) >> 1;                           // + ks
    // B x4 (pairs of n-tiles): lanes 0-7 -> (n, k0); 8-15 -> (n, k8);
    //                          16-23 -> (n+8, k0); 24-31 -> (n+8, k8)
    int brow4 = wn * 64 + (lane & 7) + ((lane & 16) >> 1);  // + p*16
    int bcol4 = (lane & 8);                                 // + ks

    for (int kt = 0; kt < 8; kt++) {
        int k0 = kt * 32;
#pragma unroll
        for (int it = 0; it < 4; it++) {
            int idx = t + it * 256;
            int row = idx >> 3, kq = idx & 7;
            float4 v = *(const float4*)(X + (size_t)(m0 + row) * 256 + k0 + kq * 4);
            uint2 hi, lo;
            cvt_hilo(v, hi, lo);
            *(uint2*)&sA[0][row][kq * 4] = hi;
            *(uint2*)&sA[1][row][kq * 4] = lo;
            float4 w = *(const float4*)(Wp + (size_t)row * 256 + k0 + kq * 4);
            cvt_hilo(w, hi, lo);
            *(uint2*)&sB[0][row][kq * 4] = hi;
            *(uint2*)&sB[1][row][kq * 4] = lo;
        }
        __syncthreads();
#pragma unroll
        for (int ks = 0; ks < 32; ks += 16) {
            uint32_t ah[2][4], al[2][4], bh[4][4], bl[4][4];
#pragma unroll
            for (int mi = 0; mi < 2; mi++) {
                uint32_t off = (uint32_t)((arow + mi * 16) * 40 + ks + acolx) * 2;
                ldmx4(ah[mi], baseA0 + off);
                ldmx4(al[mi], baseA1 + off);
            }
#pragma unroll
            for (int p = 0; p < 4; p++) {
                uint32_t off = (uint32_t)((brow4 + p * 16) * 40 + ks + bcol4) * 2;
                ldmx4(bh[p], baseB0 + off);
                ldmx4(bl[p], baseB1 + off);
            }
#pragma unroll
            for (int mi = 0; mi < 2; mi++)
#pragma unroll
                for (int ni = 0; ni < 8; ni++) {
                    const uint32_t* bph = &bh[ni >> 1][(ni & 1) * 2];
                    const uint32_t* bpl = &bl[ni >> 1][(ni & 1) * 2];
                    mma_bf16(acc[mi][ni], ah[mi], bph);
                    mma_bf16(acc[mi][ni], ah[mi], bpl);
                    mma_bf16(acc[mi][ni], al[mi], bph);
                }
        }
        __syncthreads();
    }

    // epilogue: bias, store h, fused hl/hr partial dots
    int rbase = m0 + wm * 32 + (lane >> 2);
    int cloc = wn * 64 + (lane & 3) * 2;     // col within head
    float pl[4] = {0.f, 0.f, 0.f, 0.f}, pr[4] = {0.f, 0.f, 0.f, 0.f};
#pragma unroll
    for (int mi = 0; mi < 2; mi++)
#pragma unroll
        for (int ni = 0; ni < 8; ni++) {
            int c0 = cloc + ni * 8;
            int gc = n0 + c0;
            float b0v = g_bcat[layer][gc], b1v = g_bcat[layer][gc + 1];
            float al0 = g_aL[layer][head][c0], al1 = g_aL[layer][head][c0 + 1];
            float ar0 = g_aR[layer][head][c0], ar1 = g_aR[layer][head][c0 + 1];
            int gr = rbase + mi * 16;
            float h00 = acc[mi][ni][0] + b0v, h01 = acc[mi][ni][1] + b1v;
            float h10 = acc[mi][ni][2] + b0v, h11 = acc[mi][ni][3] + b1v;
            float2 p0 = {h00, h01};
            float2 p1 = {h10, h11};
            *(float2*)&g_h[(size_t)gr * 256 + gc] = p0;
            *(float2*)&g_h[(size_t)(gr + 8) * 256 + gc] = p1;
            pl[mi * 2 + 0] += h00 * al0 + h01 * al1;
            pl[mi * 2 + 1] += h10 * al0 + h11 * al1;
            pr[mi * 2 + 0] += h00 * ar0 + h01 * ar1;
            pr[mi * 2 + 1] += h10 * ar0 + h11 * ar1;
        }
#pragma unroll
    for (int off = 1; off < 4; off <<= 1)
#pragma unroll
        for (int r = 0; r < 4; r++) {
            pl[r] += __shfl_xor_sync(0xFFFFFFFFu, pl[r], off);
            pr[r] += __shfl_xor_sync(0xFFFFFFFFu, pr[r], off);
        }
    if ((lane & 3) == 0) {
        int rloc = wm * 32 + (lane >> 2);
#pragma unroll
        for (int r = 0; r < 4; r++) {
            sHL[rloc + r * 8][wn] = pl[r];
            sHR[rloc + r * 8][wn] = pr[r];
        }
    }
    __syncthreads();
    if (t < 128) {
        g_hl[head * NR + m0 + t] = sHL[t][0] + sHL[t][1];
        g_hr[head * NR + m0 + t] = sHR[t][0] + sHR[t][1];
    }
}

// ---------------- bitonic sort with warp-register tails ----------------
__device__ __forceinline__ ull bswap_reg(ull v, int j, bool up, int i) {
    ull pv = __shfl_xor_sync(0xFFFFFFFFu, v, j);
    bool lower = ((i & j) == 0);
    return (lower == up) ? (v < pv ? v : pv) : (v > pv ? v : pv);
}

__global__ __launch_bounds__(1024) void sort_kernel()
{
    __shared__ ull kv[2048];
    int hb = blockIdx.x;
    int t = threadIdx.x;
    int base = (hb >> 3) * NR + (hb & 7) * 2048;

    auto mkkey = [](float f, int i) -> ull {
        unsigned u = __float_as_uint(f);
        u ^= (u >> 31) ? 0xFFFFFFFFu : 0x80000000u;
        return ((ull)u << 32) | (unsigned)i;
    };
    ull v1 = mkkey(g_hr[base + t], t);
    ull v2 = mkkey(g_hr[base + t + 1024], t + 1024);

#pragma unroll
    for (int k = 2; k <= 32; k <<= 1) {
        bool up1 = ((t & k) == 0);
        bool up2 = (((t + 1024) & k) == 0);
        for (int j = k >> 1; j >= 1; j >>= 1) {
            v1 = bswap_reg(v1, j, up1, t);
            v2 = bswap_reg(v2, j, up2, t + 1024);
        }
    }
    kv[t] = v1; kv[t + 1024] = v2;
    __syncthreads();

    for (int k = 64; k <= 2048; k <<= 1) {
        for (int j = k >> 1; j >= 32; j >>= 1) {
#pragma unroll
            for (int q = 0; q < 2; q++) {
                int i = t + q * 1024;
                int ixj = i ^ j;
                if (ixj > i) {
                    bool up = ((i & k) == 0);
                    ull a = kv[i], b = kv[ixj];
                    if ((a > b) == up) { kv[i] = b; kv[ixj] = a; }
                }
            }
            __syncthreads();
        }
        v1 = kv[t]; v2 = kv[t + 1024];
        bool up1 = ((t & k) == 0);
        bool up2 = (((t + 1024) & k) == 0);
        for (int j = 16; j >= 1; j >>= 1) {
            v1 = bswap_reg(v1, j, up1, t);
            v2 = bswap_reg(v2, j, up2, t + 1024);
        }
        if (k < 2048) { kv[t] = v1; kv[t + 1024] = v2; __syncthreads(); }
    }

    auto unkey = [](ull v, float* f, int* idx) {
        unsigned u = (unsigned)(v >> 32);
        u ^= (u >> 31) ? 0x80000000u : 0xFFFFFFFFu;
        *f = __uint_as_float(u);
        *idx = (int)(v & 0xFFFFFFFFu);
    };
    float f; int idx;
    unkey(v1, &f, &idx); g_rs[base + t] = f;        g_sidx[base + t] = idx;
    unkey(v2, &f, &idx); g_rs[base + t + 1024] = f; g_sidx[base + t + 1024] = idx;
}

// ---------------- chunked prefix pass A: per-chunk sums (single gather) ------
__global__ __launch_bounds__(256) void prefixA_kernel()
{
    __shared__ float ew1[2][64], ew2[2][64];
    __shared__ int   sid[2][64];
    int blk = blockIdx.x;
    int hb = blk >> 4, pair = blk & 15;
    int head = hb >> 3, b = hb & 7;
    int base = head * NR + b * 2048;
    int t = threadIdx.x;
    if (t < 128) {
        int ch = t >> 6, jj = t & 63;
        float r = g_rs[base + (2 * pair + ch) * 64 + jj];
        ew1[ch][jj] = expf(r);
        ew2[ch][jj] = expf(LRA * r);
        sid[ch][jj] = g_sidx[base + (2 * pair + ch) * 64 + jj];
    }
    __syncthreads();
    int half = t >> 7, d = t & 127;
    int chunk = 2 * pair + half;
    const float* hp = g_h + (size_t)(b * 2048) * 256 + head * 128 + d;
    float a1 = 0.f, a2 = 0.f, z1 = 0.f, z2 = 0.f;
#pragma unroll 8
    for (int j = 0; j < 64; j++) {
        float v = __ldg(hp + (size_t)sid[half][j] * 256);
        float w1 = ew1[half][j], w2 = ew2[half][j];
        a1 = fmaf(w1, v, a1);
        a2 = fmaf(w2, v, a2);
        if (d == 0) { z1 += w1; z2 += w2; }
    }
    g_CS1[hb][chunk][d] = a1;
    g_CS2[hb][chunk][d] = a2;
    if (d == 0) { g_ZC1[hb][chunk] = z1; g_ZC2[hb][chunk] = z2; }
}

// ---------------- chunked prefix pass C: write full prefixes -----------------
__global__ __launch_bounds__(256) void prefixC_kernel()
{
    __shared__ float ew1[2][64], ew2[2][64];
    __shared__ int   sid[2][64];
    int blk = blockIdx.x;
    int hb = blk >> 4, pair = blk & 15;
    int head = hb >> 3, b = hb & 7;
    int base = head * NR + b * 2048;
    int t = threadIdx.x;
    if (t < 128) {
        int ch = t >> 6, jj = t & 63;
        float r = g_rs[base + (2 * pair + ch) * 64 + jj];
        ew1[ch][jj] = expf(r);
        ew2[ch][jj] = expf(LRA * r);
        sid[ch][jj] = g_sidx[base + (2 * pair + ch) * 64 + jj];
    }
    __syncthreads();
    int half = t >> 7, d = t & 127;
    int chunk = 2 * pair + half;
    int j0 = chunk * 64;
    const float* hp = g_h + (size_t)(b * 2048) * 256 + head * 128 + d;
    float a1 = 0.f, a2 = 0.f, z1 = 0.f, z2 = 0.f;
#pragma unroll 8
    for (int c = 0; c < chunk; c++) {
        a1 += g_CS1[hb][c][d];
        a2 += g_CS2[hb][c][d];
        if (d == 0) { z1 += g_ZC1[hb][c]; z2 += g_ZC2[hb][c]; }
    }
    float* P1 = g_P1 + (size_t)base * 128 + d;
    float* P2 = g_P2 + (size_t)base * 128 + d;
#pragma unroll 8
    for (int j = 0; j < 64; j++) {
        float v = __ldg(hp + (size_t)sid[half][j] * 256);
        float w1 = ew1[half][j], w2 = ew2[half][j];
        a1 = fmaf(w1, v, a1);
        a2 = fmaf(w2, v, a2);
        P1[(size_t)(j0 + j) * 128] = a1;
        P2[(size_t)(j0 + j) * 128] = a2;
        if (d == 0) {
            z1 += w1; z2 += w2;
            g_Z1[base + j0 + j] = z1;
            g_Z2[base + j0 + j] = z2;
        }
    }
}

// ---------------- per-node O(D) lookup + ELU (hoisted scalars) ---------------
__global__ __launch_bounds__(256) void lookup_kernel(float* xout)
{
    __shared__ float s_ec[2][16], s_eac[2][16], s_wii[2][16], s_idn[2][16];
    __shared__ int   s_m[2][16];
    float* xo = xout ? xout : g_xmid;
    int b = blockIdx.y;
    int n0 = blockIdx.x * 16;
    int t = threadIdx.x;
    if (t < 32) {
        int hh = t >> 4, nn = t & 15;
        int bb = hh * NR + b * 2048;
        int row = b * 2048 + n0 + nn;
        float c = g_hl[hh * NR + row];
        float ri = g_hr[hh * NR + row];
        float thr = -c;
        const float* rs = &g_rs[bb];
        int lo = 0, hi = 2048;
        while (lo < hi) {
            int mid = (lo + hi) >> 1;
            if (rs[mid] < thr) lo = mid + 1; else hi = mid;
        }
        int m = lo;
        float ec = expf(c), eac = expf(LRA * c);
        float wii = (ri < thr) ? eac * expf(LRA * ri) : ec * expf(ri);
        float z1tot = g_Z1[bb + 2047];
        float Z1m = (m > 0) ? g_Z1[bb + m - 1] : 0.f;
        float Z2m = (m > 0) ? g_Z2[bb + m - 1] : 0.f;
        float denom = ec * (z1tot - Z1m) + eac * Z2m - wii;
        s_m[hh][nn] = m;
        s_ec[hh][nn] = ec;
        s_eac[hh][nn] = eac;
        s_wii[hh][nn] = wii;
        s_idn[hh][nn] = 1.f / denom;
    }
    __syncthreads();
    int head = t >> 7, d = t & 127;
    int base = head * NR + b * 2048;
    float p1tot = g_P1[((size_t)base + 2047) * 128 + d];
#pragma unroll 2
    for (int nn = 0; nn < 16; nn++) {
        int row = b * 2048 + n0 + nn;
        int m = s_m[head][nn];
        float ec = s_ec[head][nn], eac = s_eac[head][nn];
        float wii = s_wii[head][nn], idn = s_idn[head][nn];
        float hid = g_h[(size_t)row * 256 + head * 128 + d];
        float P1m = 0.f, P2m = 0.f;
        if (m > 0) {
            size_t off = ((size_t)base + m - 1) * 128 + d;
            P1m = g_P1[off];
            P2m = g_P2[off];
        }
        float numer = ec * (p1tot - P1m) + eac * P2m - wii * hid;
        float o = numer * idn + hid;
        xo[(size_t)row * 256 + head * 128 + d] = (o > 0.f) ? o : expm1f(o);
    }
}

// ---------------- launch ----------------
extern "C" void kernel_launch(void* const* d_in, const int* in_sizes, int n_in,
                              void* d_out, int out_size)
{
    const float* x   = (const float*)d_in[0];
    const float* W00 = (const float*)d_in[2];
    const float* b00 = (const float*)d_in[3];
    const float* a00 = (const float*)d_in[4];
    const float* W01 = (const float*)d_in[5];
    const float* b01 = (const float*)d_in[6];
    const float* a01 = (const float*)d_in[7];
    const float* W10 = (const float*)d_in[8];
    const float* b10 = (const float*)d_in[9];
    const float* a10 = (const float*)d_in[10];
    const float* W11 = (const float*)d_in[11];
    const float* b11 = (const float*)d_in[12];
    const float* a11 = (const float*)d_in[13];
    float* out = (float*)d_out;

    pack_kernel<<<64, 256>>>(W00, b00, a00, W01, b01, a01,
                             W10, b10, a10, W11, b11, a11);

    // layer 0
    gemm_mma_kernel<<<dim3(2, 128), 256>>>(x, 0);
    sort_kernel<<<16, 1024>>>();
    prefixA_kernel<<<256, 256>>>();
    prefixC_kernel<<<256, 256>>>();
    lookup_kernel<<<dim3(128, 8), 256>>>(nullptr);

    // layer 1
    gemm_mma_kernel<<<dim3(2, 128), 256>>>(nullptr, 1);
    sort_kernel<<<16, 1024>>>();
    prefixA_kernel<<<256, 256>>>();
    prefixC_kernel<<<256, 256>>>();
    lookup_kernel<<<dim3(128, 8), 256>>>(out);
}

// round 9
// speedup vs baseline: 3.4211x; 1.0321x over previous
#include <cuda_runtime.h>
#include <cuda_bf16.h>
#include <cstddef>
#include <cstdint>

#define NB 8
#define NN 2048
#define NR 16384          // NB*NN rows
#define LRA 0.2f

typedef unsigned long long ull;

// ---------------- device scratch ----------------
__device__ float g_h[NR * 256];
__device__ float g_xmid[NR * 256];
__device__ float g_WT[2][256 * 256];   // [layer][n][k]  (B operand, K-major)
__device__ float g_bcat[2][256];
__device__ float g_aL[2][2][128];
__device__ float g_aR[2][2][128];
__device__ float g_hl[2 * NR];
__device__ float g_hr[2 * NR];
__device__ float g_rs[2 * NR];
__device__ int   g_sidx[2 * NR];
__device__ ull   g_kv[2 * NR];         // sorted 512-runs (stage 1 output)
__device__ float g_P1[2 * NR * 128];
__device__ float g_P2[2 * NR * 128];
__device__ float g_Z1[2 * NR];
__device__ float g_Z2[2 * NR];
__device__ float g_CS1[16][64][128];
__device__ float g_CS2[16][64][128];
__device__ float g_ZC1[16][64];
__device__ float g_ZC2[16][64];

// ---------------- helpers ----------------
__device__ __forceinline__ uint32_t smem_u32(const void* p) {
    uint32_t a;
    asm("{ .reg .u64 tmp; cvta.to.shared.u64 tmp, %1; cvt.u32.u64 %0, tmp; }"
        : "=r"(a) : "l"(p));
    return a;
}
__device__ __forceinline__ void ldmx4(uint32_t* r, uint32_t addr) {
    asm volatile("ldmatrix.sync.aligned.m8n8.x4.shared.b16 {%0,%1,%2,%3}, [%4];"
        : "=r"(r[0]), "=r"(r[1]), "=r"(r[2]), "=r"(r[3]) : "r"(addr));
}
__device__ __forceinline__ void mma_bf16(float* c, const uint32_t* a, const uint32_t* b) {
    asm volatile("mma.sync.aligned.m16n8k16.row.col.f32.bf16.bf16.f32 "
        "{%0,%1,%2,%3}, {%4,%5,%6,%7}, {%8,%9}, {%0,%1,%2,%3};"
        : "+f"(c[0]), "+f"(c[1]), "+f"(c[2]), "+f"(c[3])
        : "r"(a[0]), "r"(a[1]), "r"(a[2]), "r"(a[3]), "r"(b[0]), "r"(b[1]));
}

// bf16 hi/lo split of a float4 -> two 8B packets
__device__ __forceinline__ void cvt_hilo(float4 v, uint2& hi, uint2& lo) {
    __nv_bfloat16 h0 = __float2bfloat16(v.x), h1 = __float2bfloat16(v.y);
    __nv_bfloat16 h2 = __float2bfloat16(v.z), h3 = __float2bfloat16(v.w);
    __nv_bfloat16 l0 = __float2bfloat16(v.x - __bfloat162float(h0));
    __nv_bfloat16 l1 = __float2bfloat16(v.y - __bfloat162float(h1));
    __nv_bfloat16 l2 = __float2bfloat16(v.z - __bfloat162float(h2));
    __nv_bfloat16 l3 = __float2bfloat16(v.w - __bfloat162float(h3));
    hi.x = ((uint32_t)__bfloat16_as_ushort(h1) << 16) | __bfloat16_as_ushort(h0);
    hi.y = ((uint32_t)__bfloat16_as_ushort(h3) << 16) | __bfloat16_as_ushort(h2);
    lo.x = ((uint32_t)__bfloat16_as_ushort(l1) << 16) | __bfloat16_as_ushort(l0);
    lo.y = ((uint32_t)__bfloat16_as_ushort(l3) << 16) | __bfloat16_as_ushort(l2);
}

// ---------------- pack: W -> WT (K-major B operand), bias, a vectors --------
__global__ void pack_kernel(
    const float* W00, const float* b00, const float* a00,
    const float* W01, const float* b01, const float* a01,
    const float* W10, const float* b10, const float* a10,
    const float* W11, const float* b11, const float* a11)
{
    const float* Ws[2][2] = {{W00, W01}, {W10, W11}};
    const float* bs[2][2] = {{b00, b01}, {b10, b11}};
    const float* as[2][2] = {{a00, a01}, {a10, a11}};
    int tid = blockIdx.x * blockDim.x + threadIdx.x;
    int nth = gridDim.x * blockDim.x;
    for (int idx = tid; idx < 2 * 256 * 256; idx += nth) {
        int layer = idx >> 16;
        int rem = idx & 0xFFFF;
        int n = rem >> 8, k = rem & 255;
        g_WT[layer][rem] = Ws[layer][n >> 7][k * 128 + (n & 127)];
    }
    for (int idx = tid; idx < 2 * 256; idx += nth) {
        int layer = idx >> 8, c = idx & 255;
        g_bcat[layer][c] = bs[layer][c >> 7][c & 127];
    }
    for (int idx = tid; idx < 2 * 2 * 128; idx += nth) {
        int layer = idx >> 8, head = (idx >> 7) & 1, d = idx & 127;
        g_aL[layer][head][d] = as[layer][head][d];
        g_aR[layer][head][d] = as[layer][head][128 + d];
    }
}

// ---------------- HMMA GEMM: h = X @ W + b  (3-pass bf16 hi/lo split) --------
// grid (2, 128), 256 threads. Block tile M=128 x N=128 (one head per bx).
// Software-pipelined global loads (next k-tile in regs during MMA phase).
__global__ __launch_bounds__(256) void gemm_mma_kernel(const float* __restrict__ Xin, int layer)
{
    __shared__ __align__(16) __nv_bfloat16 sA[2][128][40];
    __shared__ __align__(16) __nv_bfloat16 sB[2][128][40];
    __shared__ float sHL[128][2], sHR[128][2];
    const float* X = Xin ? Xin : g_xmid;
    int t = threadIdx.x, lane = t & 31, wid = t >> 5;
    int wm = wid & 3, wn = wid >> 2;
    int m0 = blockIdx.y * 128, n0 = blockIdx.x * 128;
    int head = n0 >> 7;
    const float* Wp = g_WT[layer] + (size_t)n0 * 256;

    float acc[2][8][4];
#pragma unroll
    for (int mi = 0; mi < 2; mi++)
#pragma unroll
        for (int ni = 0; ni < 8; ni++)
#pragma unroll
            for (int q = 0; q < 4; q++) acc[mi][ni][q] = 0.f;

    uint32_t baseA0 = smem_u32(&sA[0][0][0]);
    uint32_t baseA1 = smem_u32(&sA[1][0][0]);
    uint32_t baseB0 = smem_u32(&sB[0][0][0]);
    uint32_t baseB1 = smem_u32(&sB[1][0][0]);

    int arow = wm * 32 + (lane & 7) + (lane & 8);
    int acolx = (lane & 16) >> 1;
    int brow4 = wn * 64 + (lane & 7) + ((lane & 16) >> 1);
    int bcol4 = (lane & 8);

    int lrow = t >> 3, lkq = t & 7;

    float4 ra[4], rw[4];
#pragma unroll
    for (int it = 0; it < 4; it++) {
        int row = lrow + it * 32;
        ra[it] = *(const float4*)(X + (size_t)(m0 + row) * 256 + lkq * 4);
        rw[it] = *(const float4*)(Wp + (size_t)row * 256 + lkq * 4);
    }

    for (int kt = 0; kt < 8; kt++) {
#pragma unroll
        for (int it = 0; it < 4; it++) {
            int row = lrow + it * 32;
            uint2 hi, lo;
            cvt_hilo(ra[it], hi, lo);
            *(uint2*)&sA[0][row][lkq * 4] = hi;
            *(uint2*)&sA[1][row][lkq * 4] = lo;
            cvt_hilo(rw[it], hi, lo);
            *(uint2*)&sB[0][row][lkq * 4] = hi;
            *(uint2*)&sB[1][row][lkq * 4] = lo;
        }
        if (kt < 7) {
            int k0 = (kt + 1) * 32;
#pragma unroll
            for (int it = 0; it < 4; it++) {
                int row = lrow + it * 32;
                ra[it] = *(const float4*)(X + (size_t)(m0 + row) * 256 + k0 + lkq * 4);
                rw[it] = *(const float4*)(Wp + (size_t)row * 256 + k0 + lkq * 4);
            }
        }
        __syncthreads();
#pragma unroll
        for (int ks = 0; ks < 32; ks += 16) {
            uint32_t ah[2][4], al[2][4], bh[4][4], bl[4][4];
#pragma unroll
            for (int mi = 0; mi < 2; mi++) {
                uint32_t off = (uint32_t)((arow + mi * 16) * 40 + ks + acolx) * 2;
                ldmx4(ah[mi], baseA0 + off);
                ldmx4(al[mi], baseA1 + off);
            }
#pragma unroll
            for (int p = 0; p < 4; p++) {
                uint32_t off = (uint32_t)((brow4 + p * 16) * 40 + ks + bcol4) * 2;
                ldmx4(bh[p], baseB0 + off);
                ldmx4(bl[p], baseB1 + off);
            }
#pragma unroll
            for (int mi = 0; mi < 2; mi++)
#pragma unroll
                for (int ni = 0; ni < 8; ni++) {
                    const uint32_t* bph = &bh[ni >> 1][(ni & 1) * 2];
                    const uint32_t* bpl = &bl[ni >> 1][(ni & 1) * 2];
                    mma_bf16(acc[mi][ni], ah[mi], bph);
                    mma_bf16(acc[mi][ni], ah[mi], bpl);
                    mma_bf16(acc[mi][ni], al[mi], bph);
                }
        }
        __syncthreads();
    }

    // epilogue: bias, store h, fused hl/hr partial dots
    int rbase = m0 + wm * 32 + (lane >> 2);
    int cloc = wn * 64 + (lane & 3) * 2;
    float pl[4] = {0.f, 0.f, 0.f, 0.f}, pr[4] = {0.f, 0.f, 0.f, 0.f};
#pragma unroll
    for (int mi = 0; mi < 2; mi++)
#pragma unroll
        for (int ni = 0; ni < 8; ni++) {
            int c0 = cloc + ni * 8;
            int gc = n0 + c0;
            float b0v = g_bcat[layer][gc], b1v = g_bcat[layer][gc + 1];
            float al0 = g_aL[layer][head][c0], al1 = g_aL[layer][head][c0 + 1];
            float ar0 = g_aR[layer][head][c0], ar1 = g_aR[layer][head][c0 + 1];
            int gr = rbase + mi * 16;
            float h00 = acc[mi][ni][0] + b0v, h01 = acc[mi][ni][1] + b1v;
            float h10 = acc[mi][ni][2] + b0v, h11 = acc[mi][ni][3] + b1v;
            float2 p0 = {h00, h01};
            float2 p1 = {h10, h11};
            *(float2*)&g_h[(size_t)gr * 256 + gc] = p0;
            *(float2*)&g_h[(size_t)(gr + 8) * 256 + gc] = p1;
            pl[mi * 2 + 0] += h00 * al0 + h01 * al1;
            pl[mi * 2 + 1] += h10 * al0 + h11 * al1;
            pr[mi * 2 + 0] += h00 * ar0 + h01 * ar1;
            pr[mi * 2 + 1] += h10 * ar0 + h11 * ar1;
        }
#pragma unroll
    for (int off = 1; off < 4; off <<= 1)
#pragma unroll
        for (int r = 0; r < 4; r++) {
            pl[r] += __shfl_xor_sync(0xFFFFFFFFu, pl[r], off);
            pr[r] += __shfl_xor_sync(0xFFFFFFFFu, pr[r], off);
        }
    if ((lane & 3) == 0) {
        int rloc = wm * 32 + (lane >> 2);
#pragma unroll
        for (int r = 0; r < 4; r++) {
            sHL[rloc + r * 8][wn] = pl[r];
            sHR[rloc + r * 8][wn] = pr[r];
        }
    }
    __syncthreads();
    if (t < 128) {
        g_hl[head * NR + m0 + t] = sHL[t][0] + sHL[t][1];
        g_hr[head * NR + m0 + t] = sHR[t][0] + sHR[t][1];
    }
}

// ---------------- sort stage 1: bitonic sort of 512-runs (grid 64) ----------
__device__ __forceinline__ ull bswap_reg(ull v, int j, bool up, int i) {
    ull pv = __shfl_xor_sync(0xFFFFFFFFu, v, j);
    bool lower = ((i & j) == 0);
    return (lower == up) ? (v < pv ? v : pv) : (v > pv ? v : pv);
}

__global__ __launch_bounds__(512) void sortA_kernel()
{
    __shared__ ull kv[512];
    int bid = blockIdx.x;
    int sg = bid >> 2, r = bid & 3;
    int base = (sg >> 3) * NR + (sg & 7) * 2048;
    int i = threadIdx.x;
    int gi = r * 512 + i;

    unsigned u = __float_as_uint(g_hr[base + gi]);
    u ^= (u >> 31) ? 0xFFFFFFFFu : 0x80000000u;
    ull v = ((ull)u << 32) | (unsigned)gi;

#pragma unroll
    for (int k = 2; k <= 32; k <<= 1) {
        bool up = ((i & k) == 0);
        for (int j = k >> 1; j >= 1; j >>= 1)
            v = bswap_reg(v, j, up, i);
    }
    kv[i] = v;
    __syncthreads();

    for (int k = 64; k <= 512; k <<= 1) {
        for (int j = k >> 1; j >= 32; j >>= 1) {
            int ixj = i ^ j;
            if (ixj > i) {
                bool up = ((i & k) == 0);
                ull a = kv[i], b = kv[ixj];
                if ((a > b) == up) { kv[i] = b; kv[ixj] = a; }
            }
            __syncthreads();
        }
        v = kv[i];
        bool up = ((i & k) == 0);
        for (int j = 16; j >= 1; j >>= 1)
            v = bswap_reg(v, j, up, i);
        if (k < 512) { kv[i] = v; __syncthreads(); }
    }
    g_kv[base + gi] = v;
}

// ---------------- sort stage 2: 4-way merge by exact rank (grid 64) ----------
__global__ __launch_bounds__(512) void sortB_kernel()
{
    int bid = blockIdx.x;
    int sg = bid >> 2, r = bid & 3;
    int base = (sg >> 3) * NR + (sg & 7) * 2048;
    int i = threadIdx.x;
    ull v = g_kv[base + r * 512 + i];
    int rank = i;
#pragma unroll
    for (int rr = 0; rr < 4; rr++) {
        if (rr == r) continue;
        const ull* run = &g_kv[base + rr * 512];
        int lo = 0, hi = 512;
#pragma unroll
        for (int s = 0; s < 10; s++) {          // 10 steps: resolves [0,512] fully
            if (lo < hi) {
                int mid = (lo + hi) >> 1;
                if (__ldg(run + mid) < v) lo = mid + 1; else hi = mid;
            }
        }
        rank += lo;
    }
    unsigned u = (unsigned)(v >> 32);
    u ^= (u >> 31) ? 0x80000000u : 0xFFFFFFFFu;
    g_rs[base + rank] = __uint_as_float(u);
    g_sidx[base + rank] = (int)(v & 0xFFFFFFFFu);
}

// ---------------- chunked prefix pass A: per-chunk (32) sums, grid 512 -------
__global__ __launch_bounds__(256) void prefixA_kernel()
{
    __shared__ float ew1[2][32], ew2[2][32];
    __shared__ int   sid[2][32];
    int blk = blockIdx.x;
    int hb = blk >> 5, pair = blk & 31;
    int head = hb >> 3, b = hb & 7;
    int base = head * NR + b * 2048;
    int t = threadIdx.x;
    if (t < 64) {
        int ch = t >> 5, jj = t & 31;
        float r = g_rs[base + (2 * pair + ch) * 32 + jj];
        ew1[ch][jj] = expf(r);
        ew2[ch][jj] = expf(LRA * r);
        sid[ch][jj] = g_sidx[base + (2 * pair + ch) * 32 + jj];
    }
    __syncthreads();
    int half = t >> 7, d = t & 127;
    int chunk = 2 * pair + half;
    const float* hp = g_h + (size_t)(b * 2048) * 256 + head * 128 + d;
    float a1 = 0.f, a2 = 0.f, z1 = 0.f, z2 = 0.f;
#pragma unroll 8
    for (int j = 0; j < 32; j++) {
        float v = __ldg(hp + (size_t)sid[half][j] * 256);
        float w1 = ew1[half][j], w2 = ew2[half][j];
        a1 = fmaf(w1, v, a1);
        a2 = fmaf(w2, v, a2);
        if (d == 0) { z1 += w1; z2 += w2; }
    }
    g_CS1[hb][chunk][d] = a1;
    g_CS2[hb][chunk][d] = a2;
    if (d == 0) { g_ZC1[hb][chunk] = z1; g_ZC2[hb][chunk] = z2; }
}

// ---------------- chunked prefix pass C: write full prefixes, grid 512 -------
__global__ __launch_bounds__(256) void prefixC_kernel()
{
    __shared__ float ew1[2][32], ew2[2][32];
    __shared__ int   sid[2][32];
    int blk = blockIdx.x;
    int hb = blk >> 5, pair = blk & 31;
    int head = hb >> 3, b = hb & 7;
    int base = head * NR + b * 2048;
    int t = threadIdx.x;
    if (t < 64) {
        int ch = t >> 5, jj = t & 31;
        float r = g_rs[base + (2 * pair + ch) * 32 + jj];
        ew1[ch][jj] = expf(r);
        ew2[ch][jj] = expf(LRA * r);
        sid[ch][jj] = g_sidx[base + (2 * pair + ch) * 32 + jj];
    }
    __syncthreads();
    int half = t >> 7, d = t & 127;
    int chunk = 2 * pair + half;
    int j0 = chunk * 32;
    const float* hp = g_h + (size_t)(b * 2048) * 256 + head * 128 + d;
    float a1 = 0.f, a2 = 0.f, z1 = 0.f, z2 = 0.f;
#pragma unroll 8
    for (int c = 0; c < chunk; c++) {
        a1 += g_CS1[hb][c][d];
        a2 += g_CS2[hb][c][d];
        if (d == 0) { z1 += g_ZC1[hb][c]; z2 += g_ZC2[hb][c]; }
    }
    float* P1 = g_P1 + (size_t)base * 128 + d;
    float* P2 = g_P2 + (size_t)base * 128 + d;
#pragma unroll 8
    for (int j = 0; j < 32; j++) {
        float v = __ldg(hp + (size_t)sid[half][j] * 256);
        float w1 = ew1[half][j], w2 = ew2[half][j];
        a1 = fmaf(w1, v, a1);
        a2 = fmaf(w2, v, a2);
        P1[(size_t)(j0 + j) * 128] = a1;
        P2[(size_t)(j0 + j) * 128] = a2;
        if (d == 0) {
            z1 += w1; z2 += w2;
            g_Z1[base + j0 + j] = z1;
            g_Z2[base + j0 + j] = z2;
        }
    }
}

// ---------------- per-node O(D) lookup + ELU (hoisted scalars) ---------------
__global__ __launch_bounds__(256) void lookup_kernel(float* xout)
{
    __shared__ float s_ec[2][16], s_eac[2][16], s_wii[2][16], s_idn[2][16];
    __shared__ int   s_m[2][16];
    float* xo = xout ? xout : g_xmid;
    int b = blockIdx.y;
    int n0 = blockIdx.x * 16;
    int t = threadIdx.x;
    if (t < 32) {
        int hh = t >> 4, nn = t & 15;
        int bb = hh * NR + b * 2048;
        int row = b * 2048 + n0 + nn;
        float c = g_hl[hh * NR + row];
        float ri = g_hr[hh * NR + row];
        float thr = -c;
        const float* rs = &g_rs[bb];
        int lo = 0, hi = 2048;
        while (lo < hi) {
            int mid = (lo + hi) >> 1;
            if (rs[mid] < thr) lo = mid + 1; else hi = mid;
        }
        int m = lo;
        float ec = expf(c), eac = expf(LRA * c);
        float wii = (ri < thr) ? eac * expf(LRA * ri) : ec * expf(ri);
        float z1tot = g_Z1[bb + 2047];
        float Z1m = (m > 0) ? g_Z1[bb + m - 1] : 0.f;
        float Z2m = (m > 0) ? g_Z2[bb + m - 1] : 0.f;
        float denom = ec * (z1tot - Z1m) + eac * Z2m - wii;
        s_m[hh][nn] = m;
        s_ec[hh][nn] = ec;
        s_eac[hh][nn] = eac;
        s_wii[hh][nn] = wii;
        s_idn[hh][nn] = 1.f / denom;
    }
    __syncthreads();
    int head = t >> 7, d = t & 127;
    int base = head * NR + b * 2048;
    float p1tot = g_P1[((size_t)base + 2047) * 128 + d];
#pragma unroll 2
    for (int nn = 0; nn < 16; nn++) {
        int row = b * 2048 + n0 + nn;
        int m = s_m[head][nn];
        float ec = s_ec[head][nn], eac = s_eac[head][nn];
        float wii = s_wii[head][nn], idn = s_idn[head][nn];
        float hid = g_h[(size_t)row * 256 + head * 128 + d];
        float P1m = 0.f, P2m = 0.f;
        if (m > 0) {
            size_t off = ((size_t)base + m - 1) * 128 + d;
            P1m = g_P1[off];
            P2m = g_P2[off];
        }
        float numer = ec * (p1tot - P1m) + eac * P2m - wii * hid;
        float o = numer * idn + hid;
        xo[(size_t)row * 256 + head * 128 + d] = (o > 0.f) ? o : expm1f(o);
    }
}

// ---------------- launch ----------------
extern "C" void kernel_launch(void* const* d_in, const int* in_sizes, int n_in,
                              void* d_out, int out_size)
{
    const float* x   = (const float*)d_in[0];
    const float* W00 = (const float*)d_in[2];
    const float* b00 = (const float*)d_in[3];
    const float* a00 = (const float*)d_in[4];
    const float* W01 = (const float*)d_in[5];
    const float* b01 = (const float*)d_in[6];
    const float* a01 = (const float*)d_in[7];
    const float* W10 = (const float*)d_in[8];
    const float* b10 = (const float*)d_in[9];
    const float* a10 = (const float*)d_in[10];
    const float* W11 = (const float*)d_in[11];
    const float* b11 = (const float*)d_in[12];
    const float* a11 = (const float*)d_in[13];
    float* out = (float*)d_out;

    pack_kernel<<<64, 256>>>(W00, b00, a00, W01, b01, a01,
                             W10, b10, a10, W11, b11, a11);

    // layer 0
    gemm_mma_kernel<<<dim3(2, 128), 256>>>(x, 0);
    sortA_kernel<<<64, 512>>>();
    sortB_kernel<<<64, 512>>>();
    prefixA_kernel<<<512, 256>>>();
    prefixC_kernel<<<512, 256>>>();
    lookup_kernel<<<dim3(128, 8), 256>>>(nullptr);

    // layer 1
    gemm_mma_kernel<<<dim3(2, 128), 256>>>(nullptr, 1);
    sortA_kernel<<<64, 512>>>();
    sortB_kernel<<<64, 512>>>();
    prefixA_kernel<<<512, 256>>>();
    prefixC_kernel<<<512, 256>>>();
    lookup_kernel<<<dim3(128, 8), 256>>>(out);
}

// round 10
// speedup vs baseline: 3.7285x; 1.0898x over previous
#include <cuda_runtime.h>
#include <cuda_bf16.h>
#include <cstddef>
#include <cstdint>

#define NB 8
#define NN 2048
#define NR 16384          // NB*NN rows
#define LRA 0.2f

typedef unsigned long long ull;

// ---------------- device scratch ----------------
__device__ float g_h[NR * 256];
__device__ __nv_bfloat16 g_Xhi[NR * 256];   // layer input, bf16 hi
__device__ __nv_bfloat16 g_Xlo[NR * 256];   // layer input, bf16 lo
__device__ __nv_bfloat16 g_Whi[2][256 * 256]; // [layer][n][k] K-major
__device__ __nv_bfloat16 g_Wlo[2][256 * 256];
__device__ float g_bcat[2][256];
__device__ float g_aL[2][2][128];
__device__ float g_aR[2][2][128];
__device__ float g_hl[2 * NR];
__device__ float g_hr[2 * NR];
__device__ float g_rs[2 * NR];
__device__ int   g_sidx[2 * NR];
__device__ ull   g_kv[2 * NR];
__device__ float g_P1[2 * NR * 128];
__device__ float g_P2[2 * NR * 128];
__device__ float g_Z1[2 * NR];
__device__ float g_Z2[2 * NR];
__device__ float g_CS1[16][64][128];
__device__ float g_CS2[16][64][128];
__device__ float g_ZC1[16][64];
__device__ float g_ZC2[16][64];

// ---------------- helpers ----------------
__device__ __forceinline__ uint32_t smem_u32(const void* p) {
    uint32_t a;
    asm("{ .reg .u64 tmp; cvta.to.shared.u64 tmp, %1; cvt.u32.u64 %0, tmp; }"
        : "=r"(a) : "l"(p));
    return a;
}
__device__ __forceinline__ void ldmx4(uint32_t* r, uint32_t addr) {
    asm volatile("ldmatrix.sync.aligned.m8n8.x4.shared.b16 {%0,%1,%2,%3}, [%4];"
        : "=r"(r[0]), "=r"(r[1]), "=r"(r[2]), "=r"(r[3]) : "r"(addr));
}
__device__ __forceinline__ void mma_bf16(float* c, const uint32_t* a, const uint32_t* b) {
    asm volatile("mma.sync.aligned.m16n8k16.row.col.f32.bf16.bf16.f32 "
        "{%0,%1,%2,%3}, {%4,%5,%6,%7}, {%8,%9}, {%0,%1,%2,%3};"
        : "+f"(c[0]), "+f"(c[1]), "+f"(c[2]), "+f"(c[3])
        : "r"(a[0]), "r"(a[1]), "r"(a[2]), "r"(a[3]), "r"(b[0]), "r"(b[1]));
}
__device__ __forceinline__ void cpa16(uint32_t dst, const void* src) {
    asm volatile("cp.async.cg.shared.global [%0], [%1], 16;" :: "r"(dst), "l"(src));
}
#define CP_COMMIT() asm volatile("cp.async.commit_group;" ::: "memory")
#define CP_WAIT1()  asm volatile("cp.async.wait_group 1;" ::: "memory")
#define CP_WAIT0()  asm volatile("cp.async.wait_group 0;" ::: "memory")

// bf16 hi/lo split of a float4 -> two 8B packets
__device__ __forceinline__ void cvt_hilo(float4 v, uint2& hi, uint2& lo) {
    __nv_bfloat16 h0 = __float2bfloat16(v.x), h1 = __float2bfloat16(v.y);
    __nv_bfloat16 h2 = __float2bfloat16(v.z), h3 = __float2bfloat16(v.w);
    __nv_bfloat16 l0 = __float2bfloat16(v.x - __bfloat162float(h0));
    __nv_bfloat16 l1 = __float2bfloat16(v.y - __bfloat162float(h1));
    __nv_bfloat16 l2 = __float2bfloat16(v.z - __bfloat162float(h2));
    __nv_bfloat16 l3 = __float2bfloat16(v.w - __bfloat162float(h3));
    hi.x = ((uint32_t)__bfloat16_as_ushort(h1) << 16) | __bfloat16_as_ushort(h0);
    hi.y = ((uint32_t)__bfloat16_as_ushort(h3) << 16) | __bfloat16_as_ushort(h2);
    lo.x = ((uint32_t)__bfloat16_as_ushort(l1) << 16) | __bfloat16_as_ushort(l0);
    lo.y = ((uint32_t)__bfloat16_as_ushort(l3) << 16) | __bfloat16_as_ushort(l2);
}

// ---------------- pack: W -> bf16 hi/lo (K-major), bias, a vectors ----------
__global__ void pack_kernel(
    const float* W00, const float* b00, const float* a00,
    const float* W01, const float* b01, const float* a01,
    const float* W10, const float* b10, const float* a10,
    const float* W11, const float* b11, const float* a11)
{
    const float* Ws[2][2] = {{W00, W01}, {W10, W11}};
    const float* bs[2][2] = {{b00, b01}, {b10, b11}};
    const float* as[2][2] = {{a00, a01}, {a10, a11}};
    int tid = blockIdx.x * blockDim.x + threadIdx.x;
    int nth = gridDim.x * blockDim.x;
    for (int idx = tid; idx < 2 * 256 * 256; idx += nth) {
        int layer = idx >> 16;
        int rem = idx & 0xFFFF;
        int n = rem >> 8, k = rem & 255;
        float w = Ws[layer][n >> 7][k * 128 + (n & 127)];
        __nv_bfloat16 h = __float2bfloat16(w);
        __nv_bfloat16 l = __float2bfloat16(w - __bfloat162float(h));
        g_Whi[layer][rem] = h;
        g_Wlo[layer][rem] = l;
    }
    for (int idx = tid; idx < 2 * 256; idx += nth) {
        int layer = idx >> 8, c = idx & 255;
        g_bcat[layer][c] = bs[layer][c >> 7][c & 127];
    }
    for (int idx = tid; idx < 2 * 2 * 128; idx += nth) {
        int layer = idx >> 8, head = (idx >> 7) & 1, d = idx & 127;
        g_aL[layer][head][d] = as[layer][head][d];
        g_aR[layer][head][d] = as[layer][head][128 + d];
    }
}

// ---------------- cvtX: layer-0 input fp32 -> bf16 hi/lo ---------------------
__global__ __launch_bounds__(256) void cvtX_kernel(const float* __restrict__ x)
{
    int n4 = NR * 256 / 4;
    for (int i = blockIdx.x * blockDim.x + threadIdx.x; i < n4;
         i += gridDim.x * blockDim.x) {
        float4 v = ((const float4*)x)[i];
        uint2 hi, lo;
        cvt_hilo(v, hi, lo);
        *(uint2*)&g_Xhi[i * 4] = hi;
        *(uint2*)&g_Xlo[i * 4] = lo;
    }
}

// ---------------- HMMA GEMM: h = X @ W + b (3-pass bf16 split, cp.async) -----
// grid (2, 128), 256 threads. Double-buffered dynamic smem, no inline cvt.
#define TILE_B 10240   // one 128x40 bf16 tile in bytes
__device__ __forceinline__ uint32_t tile_off(int b, int w) {
    return (uint32_t)((b * 4 + w) * TILE_B);
}
__device__ __forceinline__ void issue_tile(
    uint32_t sb, int bb, int m0, int n0, int k0, int t,
    const __nv_bfloat16* Whi, const __nv_bfloat16* Wlo)
{
#pragma unroll
    for (int q = 0; q < 2; q++) {
        int cid = t + q * 256;
        int row = cid >> 2, c8 = cid & 3;
        uint32_t soff = (uint32_t)(row * 80 + c8 * 16);
        size_t gx = (size_t)(m0 + row) * 256 + k0 + c8 * 8;
        size_t gw = (size_t)(n0 + row) * 256 + k0 + c8 * 8;
        cpa16(sb + tile_off(bb, 0) + soff, g_Xhi + gx);
        cpa16(sb + tile_off(bb, 1) + soff, g_Xlo + gx);
        cpa16(sb + tile_off(bb, 2) + soff, Whi + gw);
        cpa16(sb + tile_off(bb, 3) + soff, Wlo + gw);
    }
}

__global__ __launch_bounds__(256) void gemm_mma_kernel(int layer)
{
    extern __shared__ char smem[];
    __shared__ float sHL[128][2], sHR[128][2];
    uint32_t sb = smem_u32(smem);
    int t = threadIdx.x, lane = t & 31, wid = t >> 5;
    int wm = wid & 3, wn = wid >> 2;
    int m0 = blockIdx.y * 128, n0 = blockIdx.x * 128;
    int head = n0 >> 7;
    const __nv_bfloat16* Whi = g_Whi[layer];
    const __nv_bfloat16* Wlo = g_Wlo[layer];

    float acc[2][8][4];
#pragma unroll
    for (int mi = 0; mi < 2; mi++)
#pragma unroll
        for (int ni = 0; ni < 8; ni++)
#pragma unroll
            for (int q = 0; q < 4; q++) acc[mi][ni][q] = 0.f;

    int arow = wm * 32 + (lane & 7) + (lane & 8);
    int acolx = (lane & 16) >> 1;
    int brow4 = wn * 64 + (lane & 7) + ((lane & 16) >> 1);
    int bcol4 = (lane & 8);

    issue_tile(sb, 0, m0, n0, 0, t, Whi, Wlo);
    CP_COMMIT();

    for (int kt = 0; kt < 8; kt++) {
        int bb = kt & 1;
        if (kt < 7) {
            issue_tile(sb, bb ^ 1, m0, n0, (kt + 1) * 32, t, Whi, Wlo);
            CP_COMMIT();
            CP_WAIT1();
        } else {
            CP_WAIT0();
        }
        __syncthreads();
        uint32_t bA0 = sb + tile_off(bb, 0), bA1 = sb + tile_off(bb, 1);
        uint32_t bB0 = sb + tile_off(bb, 2), bB1 = sb + tile_off(bb, 3);
#pragma unroll
        for (int ks = 0; ks < 32; ks += 16) {
            uint32_t ah[2][4], al[2][4], bh[4][4], bl[4][4];
#pragma unroll
            for (int mi = 0; mi < 2; mi++) {
                uint32_t off = (uint32_t)((arow + mi * 16) * 40 + ks + acolx) * 2;
                ldmx4(ah[mi], bA0 + off);
                ldmx4(al[mi], bA1 + off);
            }
#pragma unroll
            for (int p = 0; p < 4; p++) {
                uint32_t off = (uint32_t)((brow4 + p * 16) * 40 + ks + bcol4) * 2;
                ldmx4(bh[p], bB0 + off);
                ldmx4(bl[p], bB1 + off);
            }
#pragma unroll
            for (int mi = 0; mi < 2; mi++)
#pragma unroll
                for (int ni = 0; ni < 8; ni++) {
                    const uint32_t* bph = &bh[ni >> 1][(ni & 1) * 2];
                    const uint32_t* bpl = &bl[ni >> 1][(ni & 1) * 2];
                    mma_bf16(acc[mi][ni], ah[mi], bph);
                    mma_bf16(acc[mi][ni], ah[mi], bpl);
                    mma_bf16(acc[mi][ni], al[mi], bph);
                }
        }
        __syncthreads();
    }

    // epilogue: bias, store h, fused hl/hr partial dots
    int rbase = m0 + wm * 32 + (lane >> 2);
    int cloc = wn * 64 + (lane & 3) * 2;
    float pl[4] = {0.f, 0.f, 0.f, 0.f}, pr[4] = {0.f, 0.f, 0.f, 0.f};
#pragma unroll
    for (int mi = 0; mi < 2; mi++)
#pragma unroll
        for (int ni = 0; ni < 8; ni++) {
            int c0 = cloc + ni * 8;
            int gc = n0 + c0;
            float b0v = g_bcat[layer][gc], b1v = g_bcat[layer][gc + 1];
            float al0 = g_aL[layer][head][c0], al1 = g_aL[layer][head][c0 + 1];
            float ar0 = g_aR[layer][head][c0], ar1 = g_aR[layer][head][c0 + 1];
            int gr = rbase + mi * 16;
            float h00 = acc[mi][ni][0] + b0v, h01 = acc[mi][ni][1] + b1v;
            float h10 = acc[mi][ni][2] + b0v, h11 = acc[mi][ni][3] + b1v;
            float2 p0 = {h00, h01};
            float2 p1 = {h10, h11};
            *(float2*)&g_h[(size_t)gr * 256 + gc] = p0;
            *(float2*)&g_h[(size_t)(gr + 8) * 256 + gc] = p1;
            pl[mi * 2 + 0] += h00 * al0 + h01 * al1;
            pl[mi * 2 + 1] += h10 * al0 + h11 * al1;
            pr[mi * 2 + 0] += h00 * ar0 + h01 * ar1;
            pr[mi * 2 + 1] += h10 * ar0 + h11 * ar1;
        }
#pragma unroll
    for (int off = 1; off < 4; off <<= 1)
#pragma unroll
        for (int r = 0; r < 4; r++) {
            pl[r] += __shfl_xor_sync(0xFFFFFFFFu, pl[r], off);
            pr[r] += __shfl_xor_sync(0xFFFFFFFFu, pr[r], off);
        }
    if ((lane & 3) == 0) {
        int rloc = wm * 32 + (lane >> 2);
#pragma unroll
        for (int r = 0; r < 4; r++) {
            sHL[rloc + r * 8][wn] = pl[r];
            sHR[rloc + r * 8][wn] = pr[r];
        }
    }
    __syncthreads();
    if (t < 128) {
        g_hl[head * NR + m0 + t] = sHL[t][0] + sHL[t][1];
        g_hr[head * NR + m0 + t] = sHR[t][0] + sHR[t][1];
    }
}

// ---------------- sort stage 1: bitonic sort of 512-runs (grid 64) ----------
__device__ __forceinline__ ull bswap_reg(ull v, int j, bool up, int i) {
    ull pv = __shfl_xor_sync(0xFFFFFFFFu, v, j);
    bool lower = ((i & j) == 0);
    return (lower == up) ? (v < pv ? v : pv) : (v > pv ? v : pv);
}

__global__ __launch_bounds__(512) void sortA_kernel()
{
    __shared__ ull kv[512];
    int bid = blockIdx.x;
    int sg = bid >> 2, r = bid & 3;
    int base = (sg >> 3) * NR + (sg & 7) * 2048;
    int i = threadIdx.x;
    int gi = r * 512 + i;

    unsigned u = __float_as_uint(g_hr[base + gi]);
    u ^= (u >> 31) ? 0xFFFFFFFFu : 0x80000000u;
    ull v = ((ull)u << 32) | (unsigned)gi;

#pragma unroll
    for (int k = 2; k <= 32; k <<= 1) {
        bool up = ((i & k) == 0);
        for (int j = k >> 1; j >= 1; j >>= 1)
            v = bswap_reg(v, j, up, i);
    }
    kv[i] = v;
    __syncthreads();

    for (int k = 64; k <= 512; k <<= 1) {
        for (int j = k >> 1; j >= 32; j >>= 1) {
            int ixj = i ^ j;
            if (ixj > i) {
                bool up = ((i & k) == 0);
                ull a = kv[i], b = kv[ixj];
                if ((a > b) == up) { kv[i] = b; kv[ixj] = a; }
            }
            __syncthreads();
        }
        v = kv[i];
        bool up = ((i & k) == 0);
        for (int j = 16; j >= 1; j >>= 1)
            v = bswap_reg(v, j, up, i);
        if (k < 512) { kv[i] = v; __syncthreads(); }
    }
    g_kv[base + gi] = v;
}

// ---------------- sort stage 2: 4-way merge by exact rank, smem-staged ------
__global__ __launch_bounds__(512) void sortB_kernel()
{
    __shared__ ull runs[2048];
    int bid = blockIdx.x;
    int sg = bid >> 2, r = bid & 3;
    int base = (sg >> 3) * NR + (sg & 7) * 2048;
    int i = threadIdx.x;
#pragma unroll
    for (int q = 0; q < 4; q++)
        runs[i + q * 512] = g_kv[base + i + q * 512];
    __syncthreads();

    ull v = runs[r * 512 + i];
    int rank = i;
#pragma unroll
    for (int rr = 0; rr < 4; rr++) {
        if (rr == r) continue;
        const ull* run = &runs[rr * 512];
        int lo = 0, hi = 512;
#pragma unroll
        for (int s = 0; s < 10; s++) {
            if (lo < hi) {
                int mid = (lo + hi) >> 1;
                if (run[mid] < v) lo = mid + 1; else hi = mid;
            }
        }
        rank += lo;
    }
    unsigned u = (unsigned)(v >> 32);
    u ^= (u >> 31) ? 0x80000000u : 0xFFFFFFFFu;
    g_rs[base + rank] = __uint_as_float(u);
    g_sidx[base + rank] = (int)(v & 0xFFFFFFFFu);
}

// ---------------- chunked prefix pass A: per-chunk (32) sums, grid 512 -------
__global__ __launch_bounds__(256) void prefixA_kernel()
{
    __shared__ float ew1[2][32], ew2[2][32];
    __shared__ int   sid[2][32];
    int blk = blockIdx.x;
    int hb = blk >> 5, pair = blk & 31;
    int head = hb >> 3, b = hb & 7;
    int base = head * NR + b * 2048;
    int t = threadIdx.x;
    if (t < 64) {
        int ch = t >> 5, jj = t & 31;
        float r = g_rs[base + (2 * pair + ch) * 32 + jj];
        ew1[ch][jj] = expf(r);
        ew2[ch][jj] = expf(LRA * r);
        sid[ch][jj] = g_sidx[base + (2 * pair + ch) * 32 + jj];
    }
    __syncthreads();
    int half = t >> 7, d = t & 127;
    int chunk = 2 * pair + half;
    const float* hp = g_h + (size_t)(b * 2048) * 256 + head * 128 + d;
    float a1 = 0.f, a2 = 0.f, z1 = 0.f, z2 = 0.f;
#pragma unroll 8
    for (int j = 0; j < 32; j++) {
        float v = __ldg(hp + (size_t)sid[half][j] * 256);
        float w1 = ew1[half][j], w2 = ew2[half][j];
        a1 = fmaf(w1, v, a1);
        a2 = fmaf(w2, v, a2);
        if (d == 0) { z1 += w1; z2 += w2; }
    }
    g_CS1[hb][chunk][d] = a1;
    g_CS2[hb][chunk][d] = a2;
    if (d == 0) { g_ZC1[hb][chunk] = z1; g_ZC2[hb][chunk] = z2; }
}

// ---------------- chunked prefix pass C: write full prefixes, grid 512 -------
__global__ __launch_bounds__(256) void prefixC_kernel()
{
    __shared__ float ew1[2][32], ew2[2][32];
    __shared__ int   sid[2][32];
    int blk = blockIdx.x;
    int hb = blk >> 5, pair = blk & 31;
    int head = hb >> 3, b = hb & 7;
    int base = head * NR + b * 2048;
    int t = threadIdx.x;
    if (t < 64) {
        int ch = t >> 5, jj = t & 31;
        float r = g_rs[base + (2 * pair + ch) * 32 + jj];
        ew1[ch][jj] = expf(r);
        ew2[ch][jj] = expf(LRA * r);
        sid[ch][jj] = g_sidx[base + (2 * pair + ch) * 32 + jj];
    }
    __syncthreads();
    int half = t >> 7, d = t & 127;
    int chunk = 2 * pair + half;
    int j0 = chunk * 32;
    const float* hp = g_h + (size_t)(b * 2048) * 256 + head * 128 + d;
    float a1 = 0.f, a2 = 0.f, z1 = 0.f, z2 = 0.f;
#pragma unroll 8
    for (int c = 0; c < chunk; c++) {
        a1 += g_CS1[hb][c][d];
        a2 += g_CS2[hb][c][d];
        if (d == 0) { z1 += g_ZC1[hb][c]; z2 += g_ZC2[hb][c]; }
    }
    float* P1 = g_P1 + (size_t)base * 128 + d;
    float* P2 = g_P2 + (size_t)base * 128 + d;
#pragma unroll 8
    for (int j = 0; j < 32; j++) {
        float v = __ldg(hp + (size_t)sid[half][j] * 256);
        float w1 = ew1[half][j], w2 = ew2[half][j];
        a1 = fmaf(w1, v, a1);
        a2 = fmaf(w2, v, a2);
        P1[(size_t)(j0 + j) * 128] = a1;
        P2[(size_t)(j0 + j) * 128] = a2;
        if (d == 0) {
            z1 += w1; z2 += w2;
            g_Z1[base + j0 + j] = z1;
            g_Z2[base + j0 + j] = z2;
        }
    }
}

// ---------------- per-node O(D) lookup + ELU; mid-layer writes bf16 hi/lo ----
__global__ __launch_bounds__(256) void lookup_kernel(float* xout)
{
    __shared__ float s_ec[2][16], s_eac[2][16], s_wii[2][16], s_idn[2][16];
    __shared__ int   s_m[2][16];
    int b = blockIdx.y;
    int n0 = blockIdx.x * 16;
    int t = threadIdx.x;
    if (t < 32) {
        int hh = t >> 4, nn = t & 15;
        int bb = hh * NR + b * 2048;
        int row = b * 2048 + n0 + nn;
        float c = g_hl[hh * NR + row];
        float ri = g_hr[hh * NR + row];
        float thr = -c;
        const float* rs = &g_rs[bb];
        int lo = 0, hi = 2048;
        while (lo < hi) {
            int mid = (lo + hi) >> 1;
            if (rs[mid] < thr) lo = mid + 1; else hi = mid;
        }
        int m = lo;
        float ec = expf(c), eac = expf(LRA * c);
        float wii = (ri < thr) ? eac * expf(LRA * ri) : ec * expf(ri);
        float z1tot = g_Z1[bb + 2047];
        float Z1m = (m > 0) ? g_Z1[bb + m - 1] : 0.f;
        float Z2m = (m > 0) ? g_Z2[bb + m - 1] : 0.f;
        float denom = ec * (z1tot - Z1m) + eac * Z2m - wii;
        s_m[hh][nn] = m;
        s_ec[hh][nn] = ec;
        s_eac[hh][nn] = eac;
        s_wii[hh][nn] = wii;
        s_idn[hh][nn] = 1.f / denom;
    }
    __syncthreads();
    int head = t >> 7, d = t & 127;
    int base = head * NR + b * 2048;
    float p1tot = g_P1[((size_t)base + 2047) * 128 + d];
#pragma unroll 2
    for (int nn = 0; nn < 16; nn++) {
        int row = b * 2048 + n0 + nn;
        int m = s_m[head][nn];
        float ec = s_ec[head][nn], eac = s_eac[head][nn];
        float wii = s_wii[head][nn], idn = s_idn[head][nn];
        size_t idx = (size_t)row * 256 + head * 128 + d;
        float hid = g_h[idx];
        float P1m = 0.f, P2m = 0.f;
        if (m > 0) {
            size_t off = ((size_t)base + m - 1) * 128 + d;
            P1m = g_P1[off];
            P2m = g_P2[off];
        }
        float numer = ec * (p1tot - P1m) + eac * P2m - wii * hid;
        float o = numer * idn + hid;
        float res = (o > 0.f) ? o : expm1f(o);
        if (xout) {
            xout[idx] = res;
        } else {
            __nv_bfloat16 h = __float2bfloat16(res);
            __nv_bfloat16 l = __float2bfloat16(res - __bfloat162float(h));
            g_Xhi[idx] = h;
            g_Xlo[idx] = l;
        }
    }
}

// ---------------- launch ----------------
extern "C" void kernel_launch(void* const* d_in, const int* in_sizes, int n_in,
                              void* d_out, int out_size)
{
    const float* x   = (const float*)d_in[0];
    const float* W00 = (const float*)d_in[2];
    const float* b00 = (const float*)d_in[3];
    const float* a00 = (const float*)d_in[4];
    const float* W01 = (const float*)d_in[5];
    const float* b01 = (const float*)d_in[6];
    const float* a01 = (const float*)d_in[7];
    const float* W10 = (const float*)d_in[8];
    const float* b10 = (const float*)d_in[9];
    const float* a10 = (const float*)d_in[10];
    const float* W11 = (const float*)d_in[11];
    const float* b11 = (const float*)d_in[12];
    const float* a11 = (const float*)d_in[13];
    float* out = (float*)d_out;

    const int GEMM_SMEM = 8 * TILE_B;   // 80 KB dynamic
    cudaFuncSetAttribute(gemm_mma_kernel,
                         cudaFuncAttributeMaxDynamicSharedMemorySize, GEMM_SMEM);

    pack_kernel<<<64, 256>>>(W00, b00, a00, W01, b01, a01,
                             W10, b10, a10, W11, b11, a11);
    cvtX_kernel<<<2048, 256>>>(x);

    // layer 0
    gemm_mma_kernel<<<dim3(2, 128), 256, GEMM_SMEM>>>(0);
    sortA_kernel<<<64, 512>>>();
    sortB_kernel<<<64, 512>>>();
    prefixA_kernel<<<512, 256>>>();
    prefixC_kernel<<<512, 256>>>();
    lookup_kernel<<<dim3(128, 8), 256>>>(nullptr);

    // layer 1
    gemm_mma_kernel<<<dim3(2, 128), 256, GEMM_SMEM>>>(1);
    sortA_kernel<<<64, 512>>>();
    sortB_kernel<<<64, 512>>>();
    prefixA_kernel<<<512, 256>>>();
    prefixC_kernel<<<512, 256>>>();
    lookup_kernel<<<dim3(128, 8), 256>>>(out);
}